// round 12
// baseline (speedup 1.0000x reference)
#include <cuda_runtime.h>
#include <cuda_bf16.h>
#include <math.h>
#include <cstdint>

#define SQ   2048
#define HID  2048
#define NHK  16
#define KDIM 128
#define VDIM 256
#define NVD  4096
#define OUT_ELEMS  (SQ*HID)
#define SF_ELEMS   (NHK*KDIM*VDIM)

// ---------------- scratch -----------------------------------------------------
__device__ __align__(256) float g_v   [SQ*NVD];
__device__ __align__(256) float g_qc  [SQ*HID];
__device__ __align__(256) float g_kc  [SQ*HID];
__device__ __align__(256) float g_gate[SQ*NHK];
__device__ __align__(256) float g_beta[SQ*NHK];

__device__ __align__(256) __nv_bfloat16 g_xh [SQ*HID],  g_xl [SQ*HID];
__device__ __align__(256) __nv_bfloat16 g_wqh[HID*HID], g_wql[HID*HID];
__device__ __align__(256) __nv_bfloat16 g_wkh[HID*HID], g_wkl[HID*HID];
__device__ __align__(256) __nv_bfloat16 g_wvh[NVD*HID], g_wvl[NVD*HID];
__device__ __align__(256) __nv_bfloat16 g_woh[HID*NVD], g_wol[HID*NVD];
__device__ __align__(256) __nv_bfloat16 g_ah [SQ*NVD],  g_al [SQ*NVD];
__device__ __align__(256) __nv_bfloat16 g_qph[SQ*HID],  g_qpl[SQ*HID];
__device__ __align__(256) __nv_bfloat16 g_kph[SQ*HID],  g_kpl[SQ*HID];
__device__ __align__(256) __nv_bfloat16 g_cqh[HID*512], g_cql[HID*512];
__device__ __align__(256) __nv_bfloat16 g_ckh[HID*512], g_ckl[HID*512];
// padded [Wg;Wb] 128x2048 (rows 32..127 stay zero-initialized)
__device__ __align__(256) __nv_bfloat16 g_wgbh[128*HID], g_wgbl[128*HID];

// ---------------- PTX helpers --------------------------------------------------
__device__ __forceinline__ uint32_t smem_u32(const void* p) {
    uint32_t a;
    asm("{ .reg .u64 t; cvta.to.shared.u64 t, %1; cvt.u32.u64 %0, t; }" : "=r"(a) : "l"(p));
    return a;
}
__device__ __forceinline__ void cp16(uint32_t dst, const void* src) {
    asm volatile("cp.async.cg.shared.global [%0], [%1], 16;" :: "r"(dst), "l"(src));
}
#define CP_COMMIT() asm volatile("cp.async.commit_group;")
#define CP_WAIT(n)  asm volatile("cp.async.wait_group %0;" :: "n"(n))

__device__ __forceinline__ void ldsm_x4(uint32_t& r0, uint32_t& r1, uint32_t& r2,
                                        uint32_t& r3, uint32_t a) {
    asm volatile("ldmatrix.sync.aligned.m8n8.x4.shared.b16 {%0,%1,%2,%3}, [%4];"
                 : "=r"(r0), "=r"(r1), "=r"(r2), "=r"(r3) : "r"(a));
}
__device__ __forceinline__ void mma16816(float* d, const uint32_t* a, const uint32_t* b) {
    asm volatile(
        "mma.sync.aligned.m16n8k16.row.col.f32.bf16.bf16.f32 "
        "{%0,%1,%2,%3},{%4,%5,%6,%7},{%8,%9},{%0,%1,%2,%3};"
        : "+f"(d[0]), "+f"(d[1]), "+f"(d[2]), "+f"(d[3])
        : "r"(a[0]), "r"(a[1]), "r"(a[2]), "r"(a[3]), "r"(b[0]), "r"(b[1]));
}

// ---------------- mega split kernel -------------------------------------------
__device__ __forceinline__ void split_one(const float2* X, __nv_bfloat162* H,
                                          __nv_bfloat162* L, int i) {
    float2 x = X[i];
    __nv_bfloat16 hx = __float2bfloat16(x.x), hy = __float2bfloat16(x.y);
    float rx = x.x - __bfloat162float(hx);
    float ry = x.y - __bfloat162float(hy);
    __nv_bfloat162 h; h.x = hx; h.y = hy;
    __nv_bfloat162 l; l.x = __float2bfloat16(rx); l.y = __float2bfloat16(ry);
    H[i] = h; L[i] = l;
}

// blocks: x 8192 | wq 8192 | wk 8192 | wv 16384 | wo 16384 | convq 4096 |
//         convk 4096 | wg 64 | wb 64   (total 65664)
__global__ __launch_bounds__(256) void split_all(
        const float2* x,  const float2* wq, const float2* wk,
        const float2* wv, const float2* wo,
        const float* cwq, const float* cwk,
        const float2* wg, const float2* wb) {
    int b = blockIdx.x;
    int tid = threadIdx.x;
    if (b < 8192) {
        split_one(x, (__nv_bfloat162*)g_xh, (__nv_bfloat162*)g_xl, b * 256 + tid);
    } else if (b < 16384) {
        split_one(wq, (__nv_bfloat162*)g_wqh, (__nv_bfloat162*)g_wql, (b - 8192) * 256 + tid);
    } else if (b < 24576) {
        split_one(wk, (__nv_bfloat162*)g_wkh, (__nv_bfloat162*)g_wkl, (b - 16384) * 256 + tid);
    } else if (b < 40960) {
        split_one(wv, (__nv_bfloat162*)g_wvh, (__nv_bfloat162*)g_wvl, (b - 24576) * 256 + tid);
    } else if (b < 57344) {
        split_one(wo, (__nv_bfloat162*)g_woh, (__nv_bfloat162*)g_wol, (b - 40960) * 256 + tid);
    } else if (b < 61440) {
        int e = (b - 57344) * 256 + tid;
        int o = e >> 9, kk = e & 511, tap = kk >> 7, i = kk & 127;
        float v = cwq[o * 512 + i * 4 + tap];
        __nv_bfloat16 h = __float2bfloat16(v);
        g_cqh[e] = h;
        g_cql[e] = __float2bfloat16(v - __bfloat162float(h));
    } else if (b < 65536) {
        int e = (b - 61440) * 256 + tid;
        int o = e >> 9, kk = e & 511, tap = kk >> 7, i = kk & 127;
        float v = cwk[o * 512 + i * 4 + tap];
        __nv_bfloat16 h = __float2bfloat16(v);
        g_ckh[e] = h;
        g_ckl[e] = __float2bfloat16(v - __bfloat162float(h));
    } else if (b < 65600) {
        split_one(wg, (__nv_bfloat162*)g_wgbh, (__nv_bfloat162*)g_wgbl,
                  (b - 65536) * 256 + tid);
    } else {
        split_one(wb, ((__nv_bfloat162*)g_wgbh) + 16 * 1024,
                      ((__nv_bfloat162*)g_wgbl) + 16 * 1024,
                  (b - 65600) * 256 + tid);
    }
}

// ---------------- common GEMM pieces ------------------------------------------
// 64B rows with XOR swizzle: row r, 16B chunk c -> r*64 + (c ^ ((r>>1)&3))*16.
// 3 stages of 32KB, 2 CTAs/SM, prefetch distance 2.
#define MATB  8192u
#define STGB  (4u*MATB)      // 32768
#define GSMEM (3u*STGB)      // 98304

__device__ __forceinline__ uint32_t sw64(uint32_t row, uint32_t c) {
    return row * 64u + ((c ^ ((row >> 1) & 3u)) << 4);
}

__device__ __forceinline__ void ld_stage(uint32_t st,
        const __nv_bfloat16* __restrict__ Ah, const __nv_bfloat16* __restrict__ Al,
        const __nv_bfloat16* __restrict__ Bh, const __nv_bfloat16* __restrict__ Bl,
        int bm, int bn, int k0, int K, int t) {
#pragma unroll
    for (int i = 0; i < 8; ++i) {
        int idx = t + i * 256;
        int mat = idx >> 9;
        int j   = idx & 511;
        int row = j >> 2, c = j & 3;
        const __nv_bfloat16* base = (mat == 0) ? Ah : (mat == 1) ? Al
                                   : (mat == 2) ? Bh : Bl;
        int grow = ((mat < 2) ? bm : bn) + row;
        cp16(st + mat * MATB + sw64(row, c),
             base + (size_t)grow * K + k0 + c * 8);
    }
}

// one K=32 chunk: A frags up-front, b reused Bh -> Bl (no WAR on A).
__device__ __forceinline__ void chunk_compute(uint32_t stg, int lane, int wm, int wn,
                                              float acc[4][4][4]) {
    const uint32_t rA0 = (uint32_t)wm * 64 + (lane & 15);
    const uint32_t hiA = (uint32_t)lane >> 4;
    const uint32_t sA  = (rA0 >> 1) & 3u;
    const uint32_t rB0 = (uint32_t)wn * 32 + (((uint32_t)lane >> 4) << 3) + (lane & 7);
    const uint32_t hB  = ((uint32_t)lane >> 3) & 1u;
    const uint32_t sB  = (rB0 >> 1) & 3u;
    const uint32_t baseAh = stg + rA0 * 64;
    const uint32_t baseAl = baseAh + MATB;
    const uint32_t baseBh = stg + 2 * MATB + rB0 * 64;
    const uint32_t baseBl = baseBh + MATB;
#pragma unroll
    for (int kh = 0; kh < 2; ++kh) {
        const uint32_t cA = (((uint32_t)(kh * 2) + hiA) ^ sA) << 4;
        const uint32_t cB = (((uint32_t)(kh * 2) + hB) ^ sB) << 4;
        uint32_t ah[4][4], al[4][4], b[4][2];
#pragma unroll
        for (int mt = 0; mt < 4; ++mt) {
            ldsm_x4(ah[mt][0], ah[mt][1], ah[mt][2], ah[mt][3],
                    baseAh + mt * 1024 + cA);
            ldsm_x4(al[mt][0], al[mt][1], al[mt][2], al[mt][3],
                    baseAl + mt * 1024 + cA);
        }
#pragma unroll
        for (int p = 0; p < 2; ++p)
            ldsm_x4(b[2*p][0], b[2*p][1], b[2*p+1][0], b[2*p+1][1],
                    baseBh + p * 1024 + cB);
#pragma unroll
        for (int mt = 0; mt < 4; ++mt)
#pragma unroll
            for (int nt = 0; nt < 4; ++nt)
                mma16816(acc[mt][nt], ah[mt], b[nt]);
#pragma unroll
        for (int mt = 0; mt < 4; ++mt)
#pragma unroll
            for (int nt = 0; nt < 4; ++nt)
                mma16816(acc[mt][nt], al[mt], b[nt]);
#pragma unroll
        for (int p = 0; p < 2; ++p)
            ldsm_x4(b[2*p][0], b[2*p][1], b[2*p+1][0], b[2*p+1][1],
                    baseBl + p * 1024 + cB);
#pragma unroll
        for (int mt = 0; mt < 4; ++mt)
#pragma unroll
            for (int nt = 0; nt < 4; ++nt)
                mma16816(acc[mt][nt], ah[mt], b[nt]);
    }
}

// ---------------- fused q/k/v/gates projection --------------------------------
// blocks: [0,256) q | [256,512) k | [512,1024) v | [1024,1040) gates
__global__ __launch_bounds__(256, 2) void proj_fused(
        const __nv_bfloat16* __restrict__ WQh, const __nv_bfloat16* __restrict__ WQl,
        const __nv_bfloat16* __restrict__ WKh, const __nv_bfloat16* __restrict__ WKl,
        const __nv_bfloat16* __restrict__ WVh, const __nv_bfloat16* __restrict__ WVl,
        const float* __restrict__ bg, const float* __restrict__ bb,
        __nv_bfloat16* __restrict__ Qh, __nv_bfloat16* __restrict__ Ql,
        __nv_bfloat16* __restrict__ Kh, __nv_bfloat16* __restrict__ Kl,
        float* __restrict__ V, float* __restrict__ gate, float* __restrict__ beta) {
    extern __shared__ char smem[];
    uint32_t sb = smem_u32(smem);
    const int t = threadIdx.x, wid = t >> 5, lane = t & 31;
    const int wm = wid >> 2, wn = wid & 3;
    const __nv_bfloat16* Xh = g_xh;
    const __nv_bfloat16* Xl = g_xl;

    int bx = blockIdx.x;
    int which, bm, bn;
    const __nv_bfloat16 *Bh_, *Bl_;
    if (bx < 256)       { which = 0; bm = (bx >> 4) << 7;           bn = (bx & 15) << 7; Bh_ = WQh;   Bl_ = WQl; }
    else if (bx < 512)  { which = 1; int i = bx - 256;  bm = (i >> 4) << 7; bn = (i & 15) << 7; Bh_ = WKh; Bl_ = WKl; }
    else if (bx < 1024) { which = 2; int i = bx - 512;  bm = (i >> 5) << 7; bn = (i & 31) << 7; Bh_ = WVh; Bl_ = WVl; }
    else                { which = 3; bm = (bx - 1024) << 7; bn = 0; Bh_ = g_wgbh; Bl_ = g_wgbl; }

    float acc[4][4][4];
#pragma unroll
    for (int mt = 0; mt < 4; ++mt)
#pragma unroll
        for (int nt = 0; nt < 4; ++nt)
#pragma unroll
            for (int r = 0; r < 4; ++r) acc[mt][nt][r] = 0.f;

    const int nch = HID / 32;   // 64
    ld_stage(sb,        Xh, Xl, Bh_, Bl_, bm, bn, 0,  HID, t); CP_COMMIT();
    ld_stage(sb + STGB, Xh, Xl, Bh_, Bl_, bm, bn, 32, HID, t); CP_COMMIT();
    for (int c = 0; c < nch; ++c) {
        if (c + 1 < nch) { CP_WAIT(1); } else { CP_WAIT(0); }
        __syncthreads();
        if (c + 2 < nch) {
            ld_stage(sb + ((c + 2) % 3) * STGB, Xh, Xl, Bh_, Bl_, bm, bn,
                     (c + 2) * 32, HID, t);
            CP_COMMIT();
        }
        chunk_compute(sb + (c % 3) * STGB, lane, wm, wn, acc);
    }

    const int r0 = bm + wm * 64 + (lane >> 2);
    const int ccl = wn * 32 + (lane & 3) * 2;
    if (which < 2) {
        __nv_bfloat16* Ch = which ? Kh : Qh;
        __nv_bfloat16* Cl = which ? Kl : Ql;
#pragma unroll
        for (int mt = 0; mt < 4; ++mt)
#pragma unroll
            for (int nt = 0; nt < 4; ++nt)
#pragma unroll
                for (int half = 0; half < 2; ++half) {
                    int rr = r0 + mt * 16 + half * 8;
                    int cl = bn + ccl + nt * 8;
                    float y0 = acc[mt][nt][half * 2 + 0];
                    float y1 = acc[mt][nt][half * 2 + 1];
                    __nv_bfloat162 h, l;
                    h.x = __float2bfloat16(y0); h.y = __float2bfloat16(y1);
                    l.x = __float2bfloat16(y0 - __bfloat162float(h.x));
                    l.y = __float2bfloat16(y1 - __bfloat162float(h.y));
                    size_t o2 = ((size_t)rr * HID + cl) >> 1;
                    ((__nv_bfloat162*)Ch)[o2] = h;
                    ((__nv_bfloat162*)Cl)[o2] = l;
                }
    } else if (which == 2) {
#pragma unroll
        for (int mt = 0; mt < 4; ++mt)
#pragma unroll
            for (int nt = 0; nt < 4; ++nt) {
                int rr = r0 + mt * 16;
                int cl = bn + ccl + nt * 8;
                *(float2*)&V[(size_t)rr * NVD + cl]       = make_float2(acc[mt][nt][0], acc[mt][nt][1]);
                *(float2*)&V[(size_t)(rr + 8) * NVD + cl] = make_float2(acc[mt][nt][2], acc[mt][nt][3]);
            }
    } else {
        // gates: only warp column 0 (cols 0..31) holds real data
        if (wn == 0) {
#pragma unroll
            for (int mt = 0; mt < 4; ++mt)
#pragma unroll
                for (int nt = 0; nt < 4; ++nt)
#pragma unroll
                    for (int half = 0; half < 2; ++half) {
                        int rr = r0 + mt * 16 + half * 8;
                        int cl = (lane & 3) * 2 + nt * 8;
#pragma unroll
                        for (int e = 0; e < 2; ++e) {
                            int cc2 = cl + e;
                            float y = acc[mt][nt][half * 2 + e];
                            if (cc2 < 16) {
                                float s = 1.f / (1.f + expf(-(y + bg[cc2])));
                                gate[rr * NHK + cc2] = s;
                            } else {
                                float s = 1.f / (1.f + expf(-(y + bb[cc2 - 16])));
                                beta[rr * NHK + cc2 - 16] = s;
                            }
                        }
                    }
        }
    }
}

// ---------------- output projection -------------------------------------------
__global__ __launch_bounds__(256, 2) void gemm_mma(
        const __nv_bfloat16* __restrict__ Ah, const __nv_bfloat16* __restrict__ Al,
        const __nv_bfloat16* __restrict__ Bh, const __nv_bfloat16* __restrict__ Bl,
        float* __restrict__ C, int M, int N, int K) {
    extern __shared__ char smem[];
    uint32_t sb = smem_u32(smem);
    const int t = threadIdx.x, wid = t >> 5, lane = t & 31;
    const int wm = wid >> 2, wn = wid & 3;
    const int bm = blockIdx.y * 128, bn = blockIdx.x * 128;

    float acc[4][4][4];
#pragma unroll
    for (int mt = 0; mt < 4; ++mt)
#pragma unroll
        for (int nt = 0; nt < 4; ++nt)
#pragma unroll
            for (int r = 0; r < 4; ++r) acc[mt][nt][r] = 0.f;

    const int nch = K / 32;
    ld_stage(sb,        Ah, Al, Bh, Bl, bm, bn, 0,  K, t); CP_COMMIT();
    ld_stage(sb + STGB, Ah, Al, Bh, Bl, bm, bn, 32, K, t); CP_COMMIT();
    for (int c = 0; c < nch; ++c) {
        if (c + 1 < nch) { CP_WAIT(1); } else { CP_WAIT(0); }
        __syncthreads();
        if (c + 2 < nch) {
            ld_stage(sb + ((c + 2) % 3) * STGB, Ah, Al, Bh, Bl, bm, bn,
                     (c + 2) * 32, K, t);
            CP_COMMIT();
        }
        chunk_compute(sb + (c % 3) * STGB, lane, wm, wn, acc);
    }

    const int r0 = bm + wm * 64 + (lane >> 2);
    const int cc = bn + wn * 32 + (lane & 3) * 2;
#pragma unroll
    for (int mt = 0; mt < 4; ++mt)
#pragma unroll
        for (int nt = 0; nt < 4; ++nt) {
            int rr = r0 + mt * 16;
            int cl = cc + nt * 8;
            *(float2*)&C[(size_t)rr * N + cl]       = make_float2(acc[mt][nt][0], acc[mt][nt][1]);
            *(float2*)&C[(size_t)(rr + 8) * N + cl] = make_float2(acc[mt][nt][2], acc[mt][nt][3]);
        }
}

// ---------------- conv via split-bf16 mma -------------------------------------
__global__ __launch_bounds__(256, 2) void conv_mma(
        const float* __restrict__ bq, const float* __restrict__ bk,
        float* __restrict__ Yq, float* __restrict__ Yk) {
    extern __shared__ char smem[];
    uint32_t sb = smem_u32(smem);
    const int t = threadIdx.x, wid = t >> 5, lane = t & 31;
    const int wm = wid >> 2, wn = wid & 3;
    const int g  = blockIdx.x;
    const int bm = blockIdx.y * 128;
    const int cz = blockIdx.z;
    const __nv_bfloat16* Xh = cz ? g_kph : g_qph;
    const __nv_bfloat16* Xl = cz ? g_kpl : g_qpl;
    const __nv_bfloat16* Bh = cz ? g_ckh : g_cqh;
    const __nv_bfloat16* Bl = cz ? g_ckl : g_cql;
    const float* bias = cz ? bk : bq;
    float* Y = cz ? Yk : Yq;

    float acc[4][4][4];
#pragma unroll
    for (int mt = 0; mt < 4; ++mt)
#pragma unroll
        for (int nt = 0; nt < 4; ++nt)
#pragma unroll
            for (int r = 0; r < 4; ++r) acc[mt][nt][r] = 0.f;

    auto load_chunk = [&](uint32_t st, int k0) {
        int tap = k0 >> 7, i0 = k0 & 127;
#pragma unroll
        for (int i = 0; i < 8; ++i) {
            int idx = t + i * 256;
            int mat = idx >> 9;
            int j   = idx & 511;
            int row = j >> 2, c = j & 3;
            uint32_t dst = st + mat * MATB + sw64(row, c);
            if (mat < 2) {
                int s = bm + row - 3 + tap;
                const __nv_bfloat16* base = (mat == 0) ? Xh : Xl;
                if (s >= 0)
                    cp16(dst, base + (size_t)s * HID + g * 128 + i0 + c * 8);
                else
                    *(uint4*)(smem + (dst - sb)) = make_uint4(0, 0, 0, 0);
            } else {
                const __nv_bfloat16* base = (mat == 2) ? Bh : Bl;
                cp16(dst, base + (size_t)(g * 128 + row) * 512 + k0 + c * 8);
            }
        }
    };

    const int nch = 16;
    load_chunk(sb, 0);         CP_COMMIT();
    load_chunk(sb + STGB, 32); CP_COMMIT();
    for (int c = 0; c < nch; ++c) {
        if (c + 1 < nch) { CP_WAIT(1); } else { CP_WAIT(0); }
        __syncthreads();
        if (c + 2 < nch) {
            load_chunk(sb + ((c + 2) % 3) * STGB, (c + 2) * 32);
            CP_COMMIT();
        }
        chunk_compute(sb + (c % 3) * STGB, lane, wm, wn, acc);
    }

    const int r0 = bm + wm * 64 + (lane >> 2);
    const int c0 = wn * 32 + (lane & 3) * 2;
#pragma unroll
    for (int mt = 0; mt < 4; ++mt)
#pragma unroll
        for (int nt = 0; nt < 4; ++nt) {
            int cl = c0 + nt * 8;
            float b0 = bias[g * 128 + cl], b1 = bias[g * 128 + cl + 1];
#pragma unroll
            for (int half = 0; half < 2; ++half) {
                int rr = r0 + mt * 16 + half * 8;
                float y0 = acc[mt][nt][half * 2 + 0] + b0;
                float y1 = acc[mt][nt][half * 2 + 1] + b1;
                y0 = y0 / (1.f + expf(-y0));
                y1 = y1 / (1.f + expf(-y1));
                *(float2*)&Y[(size_t)rr * HID + g * 128 + cl] = make_float2(y0, y1);
            }
        }
}

// ---------------- sequential gated scan (split bf16 output) -------------------
__global__ __launch_bounds__(256) void scan_kernel(const float* __restrict__ Q,
        const float* __restrict__ K, const float* __restrict__ V,
        const float* __restrict__ Beta, const float* __restrict__ Gate,
        __nv_bfloat16* __restrict__ Oh, __nv_bfloat16* __restrict__ Ol,
        float* __restrict__ Sf) {
    __shared__ float qs[32][128];
    __shared__ float ks[32][128];
    __shared__ float vs[32][32];
    __shared__ float bs[32], gs[32];
    const int h  = blockIdx.x >> 3;
    const int c0 = (blockIdx.x & 7) * 32;
    const int t  = threadIdx.x;
    const int rg = t & 15;
    const int cg = t >> 4;

    float S0[8], S1[8];
#pragma unroll
    for (int a = 0; a < 8; ++a) { S0[a] = 0.f; S1[a] = 0.f; }

    for (int s0 = 0; s0 < SQ; s0 += 32) {
        for (int idx = t; idx < 32 * 128; idx += 256) {
            int tt = idx >> 7, col = idx & 127;
            qs[tt][col] = Q[(size_t)(s0 + tt) * HID + h * 128 + col];
            ks[tt][col] = K[(size_t)(s0 + tt) * HID + h * 128 + col];
        }
        for (int idx = t; idx < 32 * 32; idx += 256) {
            int tt = idx >> 5, col = idx & 31;
            vs[tt][col] = V[(size_t)(s0 + tt) * NVD + h * 256 + c0 + col];
        }
        if (t < 32) {
            bs[t] = Beta[(s0 + t) * NHK + h];
            gs[t] = Gate[(s0 + t) * NHK + h];
        }
        __syncthreads();
        for (int tt = 0; tt < 32; ++tt) {
            float bt = bs[tt];
            float v0 = vs[tt][cg * 2 + 0];
            float v1 = vs[tt][cg * 2 + 1];
            float p0 = 0.f, p1 = 0.f;
#pragma unroll
            for (int a = 0; a < 8; ++a) {
                float kr = ks[tt][rg + 16 * a];
                float qr = qs[tt][rg + 16 * a];
                S0[a] = bt * S0[a] + kr * v0;
                S1[a] = bt * S1[a] + kr * v1;
                p0 += qr * S0[a];
                p1 += qr * S1[a];
            }
#pragma unroll
            for (int off = 8; off; off >>= 1) {
                p0 += __shfl_xor_sync(0xffffffffu, p0, off);
                p1 += __shfl_xor_sync(0xffffffffu, p1, off);
            }
            if (rg == 0) {
                float gt = gs[tt];
                float y0 = gt * p0, y1 = gt * p1;
                __nv_bfloat162 hv, lv;
                hv.x = __float2bfloat16(y0); hv.y = __float2bfloat16(y1);
                lv.x = __float2bfloat16(y0 - __bfloat162float(hv.x));
                lv.y = __float2bfloat16(y1 - __bfloat162float(hv.y));
                size_t o2 = ((size_t)(s0 + tt) * NVD + h * 256 + c0 + cg * 2) >> 1;
                ((__nv_bfloat162*)Oh)[o2] = hv;
                ((__nv_bfloat162*)Ol)[o2] = lv;
            }
        }
        __syncthreads();
    }
    if (Sf != nullptr) {
#pragma unroll
        for (int a = 0; a < 8; ++a) {
            size_t base = (size_t)h * KDIM * VDIM + (size_t)(rg + 16 * a) * VDIM
                        + c0 + cg * 2;
            Sf[base]     = S0[a];
            Sf[base + 1] = S1[a];
        }
    }
}

// ---------------- launch ------------------------------------------------------
extern "C" void kernel_launch(void* const* d_in, const int* in_sizes, int n_in,
                              void* d_out, int out_size) {
    const float* x   = (const float*)d_in[0];
    const float* Wq  = (const float*)d_in[1];
    const float* Wk  = (const float*)d_in[2];
    const float* Wv  = (const float*)d_in[3];
    const float* Wo  = (const float*)d_in[4];
    const float* Wqc = (const float*)d_in[5];
    const float* bqc = (const float*)d_in[6];
    const float* Wkc = (const float*)d_in[7];
    const float* bkc = (const float*)d_in[8];
    const float* Wg  = (const float*)d_in[9];
    const float* bg  = (const float*)d_in[10];
    const float* Wb  = (const float*)d_in[11];
    const float* bb  = (const float*)d_in[12];
    float* out = (float*)d_out;

    float *dv, *dqc, *dkc, *dgate, *dbeta;
    cudaGetSymbolAddress((void**)&dv,    g_v);
    cudaGetSymbolAddress((void**)&dqc,   g_qc);
    cudaGetSymbolAddress((void**)&dkc,   g_kc);
    cudaGetSymbolAddress((void**)&dgate, g_gate);
    cudaGetSymbolAddress((void**)&dbeta, g_beta);

    __nv_bfloat16 *wqh, *wql, *wkh, *wkl, *wvh, *wvl, *woh, *wol, *ah, *al;
    __nv_bfloat16 *qph, *qpl, *kph, *kpl;
    cudaGetSymbolAddress((void**)&wqh, g_wqh); cudaGetSymbolAddress((void**)&wql, g_wql);
    cudaGetSymbolAddress((void**)&wkh, g_wkh); cudaGetSymbolAddress((void**)&wkl, g_wkl);
    cudaGetSymbolAddress((void**)&wvh, g_wvh); cudaGetSymbolAddress((void**)&wvl, g_wvl);
    cudaGetSymbolAddress((void**)&woh, g_woh); cudaGetSymbolAddress((void**)&wol, g_wol);
    cudaGetSymbolAddress((void**)&ah,  g_ah);  cudaGetSymbolAddress((void**)&al,  g_al);
    cudaGetSymbolAddress((void**)&qph, g_qph); cudaGetSymbolAddress((void**)&qpl, g_qpl);
    cudaGetSymbolAddress((void**)&kph, g_kph); cudaGetSymbolAddress((void**)&kpl, g_kpl);

    cudaFuncSetAttribute(proj_fused, cudaFuncAttributeMaxDynamicSharedMemorySize, GSMEM);
    cudaFuncSetAttribute(gemm_mma,   cudaFuncAttributeMaxDynamicSharedMemorySize, GSMEM);
    cudaFuncSetAttribute(conv_mma,   cudaFuncAttributeMaxDynamicSharedMemorySize, GSMEM);

    dim3 blk(256);
    // 0: mega split (x, weights, conv weights reshaped, [Wg;Wb])
    split_all<<<65664, blk>>>(
        (const float2*)x, (const float2*)Wq, (const float2*)Wk,
        (const float2*)Wv, (const float2*)Wo, Wqc, Wkc,
        (const float2*)Wg, (const float2*)Wb);
    // 1: fused q/k/v/gates projections
    proj_fused<<<1040, blk, GSMEM>>>(wqh, wql, wkh, wkl, wvh, wvl,
                                     bg, bb, qph, qpl, kph, kpl,
                                     dv, dgate, dbeta);
    // 2: both convs
    conv_mma<<<dim3(16, 16, 2), blk, GSMEM>>>(bqc, bkc, dqc, dkc);
    // 3: recurrent scan (profiled launch)
    float* Sf = (out_size >= OUT_ELEMS + SF_ELEMS) ? (out + OUT_ELEMS) : nullptr;
    scan_kernel<<<128, blk>>>(dqc, dkc, dv, dbeta, dgate, ah, al, Sf);
    // 4: output projection
    gemm_mma<<<dim3(HID/128, SQ/128), blk, GSMEM>>>(ah, al, woh, wol,
        out, SQ, HID, NVD);
}

// round 13
// speedup vs baseline: 1.4639x; 1.4639x over previous
#include <cuda_runtime.h>
#include <cuda_bf16.h>
#include <math.h>
#include <cstdint>

#define SQ   2048
#define HID  2048
#define NHK  16
#define KDIM 128
#define VDIM 256
#define NVD  4096
#define OUT_ELEMS  (SQ*HID)
#define SF_ELEMS   (NHK*KDIM*VDIM)

// ---------------- scratch -----------------------------------------------------
__device__ __align__(256) float g_v   [SQ*NVD];
__device__ __align__(256) float g_qc  [SQ*HID];
__device__ __align__(256) float g_kc  [SQ*HID];
__device__ __align__(256) float g_gate[SQ*NHK];
__device__ __align__(256) float g_beta[SQ*NHK];

__device__ __align__(256) __nv_bfloat16 g_xh [SQ*HID],  g_xl [SQ*HID];
__device__ __align__(256) __nv_bfloat16 g_wqh[HID*HID], g_wql[HID*HID];
__device__ __align__(256) __nv_bfloat16 g_wkh[HID*HID], g_wkl[HID*HID];
__device__ __align__(256) __nv_bfloat16 g_wvh[NVD*HID], g_wvl[NVD*HID];
__device__ __align__(256) __nv_bfloat16 g_woh[HID*NVD], g_wol[HID*NVD];
__device__ __align__(256) __nv_bfloat16 g_ah [SQ*NVD],  g_al [SQ*NVD];
__device__ __align__(256) __nv_bfloat16 g_qph[SQ*HID],  g_qpl[SQ*HID];
__device__ __align__(256) __nv_bfloat16 g_kph[SQ*HID],  g_kpl[SQ*HID];
__device__ __align__(256) __nv_bfloat16 g_cqh[HID*512], g_cql[HID*512];
__device__ __align__(256) __nv_bfloat16 g_ckh[HID*512], g_ckl[HID*512];

// ---------------- PTX helpers --------------------------------------------------
__device__ __forceinline__ uint32_t smem_u32(const void* p) {
    uint32_t a;
    asm("{ .reg .u64 t; cvta.to.shared.u64 t, %1; cvt.u32.u64 %0, t; }" : "=r"(a) : "l"(p));
    return a;
}
__device__ __forceinline__ void cp16(uint32_t dst, const void* src) {
    asm volatile("cp.async.cg.shared.global [%0], [%1], 16;" :: "r"(dst), "l"(src));
}
#define CP_COMMIT() asm volatile("cp.async.commit_group;")
#define CP_WAIT(n)  asm volatile("cp.async.wait_group %0;" :: "n"(n))

__device__ __forceinline__ void ldsm_x4(uint32_t& r0, uint32_t& r1, uint32_t& r2,
                                        uint32_t& r3, uint32_t a) {
    asm volatile("ldmatrix.sync.aligned.m8n8.x4.shared.b16 {%0,%1,%2,%3}, [%4];"
                 : "=r"(r0), "=r"(r1), "=r"(r2), "=r"(r3) : "r"(a));
}
__device__ __forceinline__ void mma16816(float* d, const uint32_t* a, const uint32_t* b) {
    asm volatile(
        "mma.sync.aligned.m16n8k16.row.col.f32.bf16.bf16.f32 "
        "{%0,%1,%2,%3},{%4,%5,%6,%7},{%8,%9},{%0,%1,%2,%3};"
        : "+f"(d[0]), "+f"(d[1]), "+f"(d[2]), "+f"(d[3])
        : "r"(a[0]), "r"(a[1]), "r"(a[2]), "r"(a[3]), "r"(b[0]), "r"(b[1]));
}

// ---------------- mega split kernel -------------------------------------------
__device__ __forceinline__ void split_one(const float2* X, __nv_bfloat162* H,
                                          __nv_bfloat162* L, int i) {
    float2 x = X[i];
    __nv_bfloat16 hx = __float2bfloat16(x.x), hy = __float2bfloat16(x.y);
    float rx = x.x - __bfloat162float(hx);
    float ry = x.y - __bfloat162float(hy);
    __nv_bfloat162 h; h.x = hx; h.y = hy;
    __nv_bfloat162 l; l.x = __float2bfloat16(rx); l.y = __float2bfloat16(ry);
    H[i] = h; L[i] = l;
}

// blocks: x 8192 | wq 8192 | wk 8192 | wv 16384 | wo 16384 | convq 4096 | convk 4096
__global__ __launch_bounds__(256) void split_all(
        const float2* x,  const float2* wq, const float2* wk,
        const float2* wv, const float2* wo,
        const float* cwq, const float* cwk) {
    int b = blockIdx.x;
    int tid = threadIdx.x;
    if (b < 8192) {
        split_one(x, (__nv_bfloat162*)g_xh, (__nv_bfloat162*)g_xl, b * 256 + tid);
    } else if (b < 16384) {
        split_one(wq, (__nv_bfloat162*)g_wqh, (__nv_bfloat162*)g_wql, (b - 8192) * 256 + tid);
    } else if (b < 24576) {
        split_one(wk, (__nv_bfloat162*)g_wkh, (__nv_bfloat162*)g_wkl, (b - 16384) * 256 + tid);
    } else if (b < 40960) {
        split_one(wv, (__nv_bfloat162*)g_wvh, (__nv_bfloat162*)g_wvl, (b - 24576) * 256 + tid);
    } else if (b < 57344) {
        split_one(wo, (__nv_bfloat162*)g_woh, (__nv_bfloat162*)g_wol, (b - 40960) * 256 + tid);
    } else if (b < 61440) {
        int e = (b - 57344) * 256 + tid;
        int o = e >> 9, kk = e & 511, tap = kk >> 7, i = kk & 127;
        float v = cwq[o * 512 + i * 4 + tap];
        __nv_bfloat16 h = __float2bfloat16(v);
        g_cqh[e] = h;
        g_cql[e] = __float2bfloat16(v - __bfloat162float(h));
    } else {
        int e = (b - 61440) * 256 + tid;
        int o = e >> 9, kk = e & 511, tap = kk >> 7, i = kk & 127;
        float v = cwk[o * 512 + i * 4 + tap];
        __nv_bfloat16 h = __float2bfloat16(v);
        g_ckh[e] = h;
        g_ckl[e] = __float2bfloat16(v - __bfloat162float(h));
    }
}

// ---------------- common GEMM pieces ------------------------------------------
// 64B rows with XOR swizzle: row r, 16B chunk c -> r*64 + (c ^ ((r>>1)&3))*16.
// 3 stages of 32KB, 2 CTAs/SM, prefetch distance 2.
#define MATB  8192u
#define STGB  (4u*MATB)      // 32768
#define GSMEM (3u*STGB)      // 98304

__device__ __forceinline__ uint32_t sw64(uint32_t row, uint32_t c) {
    return row * 64u + ((c ^ ((row >> 1) & 3u)) << 4);
}

__device__ __forceinline__ void ld_stage(uint32_t st,
        const __nv_bfloat16* __restrict__ Ah, const __nv_bfloat16* __restrict__ Al,
        const __nv_bfloat16* __restrict__ Bh, const __nv_bfloat16* __restrict__ Bl,
        int bm, int bn, int k0, int K, int t) {
#pragma unroll
    for (int i = 0; i < 8; ++i) {
        int idx = t + i * 256;
        int mat = idx >> 9;
        int j   = idx & 511;
        int row = j >> 2, c = j & 3;
        const __nv_bfloat16* base = (mat == 0) ? Ah : (mat == 1) ? Al
                                   : (mat == 2) ? Bh : Bl;
        int grow = ((mat < 2) ? bm : bn) + row;
        cp16(st + mat * MATB + sw64(row, c),
             base + (size_t)grow * K + k0 + c * 8);
    }
}

// one K=32 chunk: A frags up-front, b reused Bh -> Bl (no WAR on A).
__device__ __forceinline__ void chunk_compute(uint32_t stg, int lane, int wm, int wn,
                                              float acc[4][4][4]) {
    const uint32_t rA0 = (uint32_t)wm * 64 + (lane & 15);
    const uint32_t hiA = (uint32_t)lane >> 4;
    const uint32_t sA  = (rA0 >> 1) & 3u;
    const uint32_t rB0 = (uint32_t)wn * 32 + (((uint32_t)lane >> 4) << 3) + (lane & 7);
    const uint32_t hB  = ((uint32_t)lane >> 3) & 1u;
    const uint32_t sB  = (rB0 >> 1) & 3u;
    const uint32_t baseAh = stg + rA0 * 64;
    const uint32_t baseAl = baseAh + MATB;
    const uint32_t baseBh = stg + 2 * MATB + rB0 * 64;
    const uint32_t baseBl = baseBh + MATB;
#pragma unroll
    for (int kh = 0; kh < 2; ++kh) {
        const uint32_t cA = (((uint32_t)(kh * 2) + hiA) ^ sA) << 4;
        const uint32_t cB = (((uint32_t)(kh * 2) + hB) ^ sB) << 4;
        uint32_t ah[4][4], al[4][4], b[4][2];
#pragma unroll
        for (int mt = 0; mt < 4; ++mt) {
            ldsm_x4(ah[mt][0], ah[mt][1], ah[mt][2], ah[mt][3],
                    baseAh + mt * 1024 + cA);
            ldsm_x4(al[mt][0], al[mt][1], al[mt][2], al[mt][3],
                    baseAl + mt * 1024 + cA);
        }
#pragma unroll
        for (int p = 0; p < 2; ++p)
            ldsm_x4(b[2*p][0], b[2*p][1], b[2*p+1][0], b[2*p+1][1],
                    baseBh + p * 1024 + cB);
#pragma unroll
        for (int mt = 0; mt < 4; ++mt)
#pragma unroll
            for (int nt = 0; nt < 4; ++nt)
                mma16816(acc[mt][nt], ah[mt], b[nt]);
#pragma unroll
        for (int mt = 0; mt < 4; ++mt)
#pragma unroll
            for (int nt = 0; nt < 4; ++nt)
                mma16816(acc[mt][nt], al[mt], b[nt]);
#pragma unroll
        for (int p = 0; p < 2; ++p)
            ldsm_x4(b[2*p][0], b[2*p][1], b[2*p+1][0], b[2*p+1][1],
                    baseBl + p * 1024 + cB);
#pragma unroll
        for (int mt = 0; mt < 4; ++mt)
#pragma unroll
            for (int nt = 0; nt < 4; ++nt)
                mma16816(acc[mt][nt], ah[mt], b[nt]);
    }
}

// ---------------- fused q/k/v projection --------------------------------------
__global__ __launch_bounds__(256, 2) void proj_fused(
        const __nv_bfloat16* __restrict__ Xh, const __nv_bfloat16* __restrict__ Xl,
        const __nv_bfloat16* __restrict__ WQh, const __nv_bfloat16* __restrict__ WQl,
        const __nv_bfloat16* __restrict__ WKh, const __nv_bfloat16* __restrict__ WKl,
        const __nv_bfloat16* __restrict__ WVh, const __nv_bfloat16* __restrict__ WVl,
        __nv_bfloat16* __restrict__ Qh, __nv_bfloat16* __restrict__ Ql,
        __nv_bfloat16* __restrict__ Kh, __nv_bfloat16* __restrict__ Kl,
        float* __restrict__ V) {
    extern __shared__ char smem[];
    uint32_t sb = smem_u32(smem);
    const int t = threadIdx.x, wid = t >> 5, lane = t & 31;
    const int wm = wid >> 2, wn = wid & 3;

    int bx = blockIdx.x;
    int which, bm, bn;
    const __nv_bfloat16 *Bh_, *Bl_;
    if (bx < 256)      { which = 0; bm = (bx >> 4) << 7;          bn = (bx & 15) << 7; Bh_ = WQh; Bl_ = WQl; }
    else if (bx < 512) { which = 1; int i = bx - 256; bm = (i >> 4) << 7; bn = (i & 15) << 7; Bh_ = WKh; Bl_ = WKl; }
    else               { which = 2; int i = bx - 512; bm = (i >> 5) << 7; bn = (i & 31) << 7; Bh_ = WVh; Bl_ = WVl; }

    float acc[4][4][4];
#pragma unroll
    for (int mt = 0; mt < 4; ++mt)
#pragma unroll
        for (int nt = 0; nt < 4; ++nt)
#pragma unroll
            for (int r = 0; r < 4; ++r) acc[mt][nt][r] = 0.f;

    const int nch = HID / 32;   // 64
    ld_stage(sb,        Xh, Xl, Bh_, Bl_, bm, bn, 0,  HID, t); CP_COMMIT();
    ld_stage(sb + STGB, Xh, Xl, Bh_, Bl_, bm, bn, 32, HID, t); CP_COMMIT();
    for (int c = 0; c < nch; ++c) {
        if (c + 1 < nch) { CP_WAIT(1); } else { CP_WAIT(0); }
        __syncthreads();
        if (c + 2 < nch) {
            ld_stage(sb + ((c + 2) % 3) * STGB, Xh, Xl, Bh_, Bl_, bm, bn,
                     (c + 2) * 32, HID, t);
            CP_COMMIT();
        }
        chunk_compute(sb + (c % 3) * STGB, lane, wm, wn, acc);
    }

    const int r0 = bm + wm * 64 + (lane >> 2);
    const int ccl = wn * 32 + (lane & 3) * 2;
    if (which < 2) {
        __nv_bfloat16* Ch = which ? Kh : Qh;
        __nv_bfloat16* Cl = which ? Kl : Ql;
#pragma unroll
        for (int mt = 0; mt < 4; ++mt)
#pragma unroll
            for (int nt = 0; nt < 4; ++nt)
#pragma unroll
                for (int half = 0; half < 2; ++half) {
                    int rr = r0 + mt * 16 + half * 8;
                    int cl = bn + ccl + nt * 8;
                    float y0 = acc[mt][nt][half * 2 + 0];
                    float y1 = acc[mt][nt][half * 2 + 1];
                    __nv_bfloat162 h, l;
                    h.x = __float2bfloat16(y0); h.y = __float2bfloat16(y1);
                    l.x = __float2bfloat16(y0 - __bfloat162float(h.x));
                    l.y = __float2bfloat16(y1 - __bfloat162float(h.y));
                    size_t o2 = ((size_t)rr * HID + cl) >> 1;
                    ((__nv_bfloat162*)Ch)[o2] = h;
                    ((__nv_bfloat162*)Cl)[o2] = l;
                }
    } else {
#pragma unroll
        for (int mt = 0; mt < 4; ++mt)
#pragma unroll
            for (int nt = 0; nt < 4; ++nt) {
                int rr = r0 + mt * 16;
                int cl = bn + ccl + nt * 8;
                *(float2*)&V[(size_t)rr * NVD + cl]       = make_float2(acc[mt][nt][0], acc[mt][nt][1]);
                *(float2*)&V[(size_t)(rr + 8) * NVD + cl] = make_float2(acc[mt][nt][2], acc[mt][nt][3]);
            }
    }
}

// ---------------- output projection -------------------------------------------
__global__ __launch_bounds__(256, 2) void gemm_mma(
        const __nv_bfloat16* __restrict__ Ah, const __nv_bfloat16* __restrict__ Al,
        const __nv_bfloat16* __restrict__ Bh, const __nv_bfloat16* __restrict__ Bl,
        float* __restrict__ C, int M, int N, int K) {
    extern __shared__ char smem[];
    uint32_t sb = smem_u32(smem);
    const int t = threadIdx.x, wid = t >> 5, lane = t & 31;
    const int wm = wid >> 2, wn = wid & 3;
    const int bm = blockIdx.y * 128, bn = blockIdx.x * 128;

    float acc[4][4][4];
#pragma unroll
    for (int mt = 0; mt < 4; ++mt)
#pragma unroll
        for (int nt = 0; nt < 4; ++nt)
#pragma unroll
            for (int r = 0; r < 4; ++r) acc[mt][nt][r] = 0.f;

    const int nch = K / 32;
    ld_stage(sb,        Ah, Al, Bh, Bl, bm, bn, 0,  K, t); CP_COMMIT();
    ld_stage(sb + STGB, Ah, Al, Bh, Bl, bm, bn, 32, K, t); CP_COMMIT();
    for (int c = 0; c < nch; ++c) {
        if (c + 1 < nch) { CP_WAIT(1); } else { CP_WAIT(0); }
        __syncthreads();
        if (c + 2 < nch) {
            ld_stage(sb + ((c + 2) % 3) * STGB, Ah, Al, Bh, Bl, bm, bn,
                     (c + 2) * 32, K, t);
            CP_COMMIT();
        }
        chunk_compute(sb + (c % 3) * STGB, lane, wm, wn, acc);
    }

    const int r0 = bm + wm * 64 + (lane >> 2);
    const int cc = bn + wn * 32 + (lane & 3) * 2;
#pragma unroll
    for (int mt = 0; mt < 4; ++mt)
#pragma unroll
        for (int nt = 0; nt < 4; ++nt) {
            int rr = r0 + mt * 16;
            int cl = cc + nt * 8;
            *(float2*)&C[(size_t)rr * N + cl]       = make_float2(acc[mt][nt][0], acc[mt][nt][1]);
            *(float2*)&C[(size_t)(rr + 8) * N + cl] = make_float2(acc[mt][nt][2], acc[mt][nt][3]);
        }
}

// ---------------- conv via split-bf16 mma -------------------------------------
__global__ __launch_bounds__(256, 2) void conv_mma(
        const float* __restrict__ bq, const float* __restrict__ bk,
        float* __restrict__ Yq, float* __restrict__ Yk) {
    extern __shared__ char smem[];
    uint32_t sb = smem_u32(smem);
    const int t = threadIdx.x, wid = t >> 5, lane = t & 31;
    const int wm = wid >> 2, wn = wid & 3;
    const int g  = blockIdx.x;
    const int bm = blockIdx.y * 128;
    const int cz = blockIdx.z;
    const __nv_bfloat16* Xh = cz ? g_kph : g_qph;
    const __nv_bfloat16* Xl = cz ? g_kpl : g_qpl;
    const __nv_bfloat16* Bh = cz ? g_ckh : g_cqh;
    const __nv_bfloat16* Bl = cz ? g_ckl : g_cql;
    const float* bias = cz ? bk : bq;
    float* Y = cz ? Yk : Yq;

    float acc[4][4][4];
#pragma unroll
    for (int mt = 0; mt < 4; ++mt)
#pragma unroll
        for (int nt = 0; nt < 4; ++nt)
#pragma unroll
            for (int r = 0; r < 4; ++r) acc[mt][nt][r] = 0.f;

    auto load_chunk = [&](uint32_t st, int k0) {
        int tap = k0 >> 7, i0 = k0 & 127;
#pragma unroll
        for (int i = 0; i < 8; ++i) {
            int idx = t + i * 256;
            int mat = idx >> 9;
            int j   = idx & 511;
            int row = j >> 2, c = j & 3;
            uint32_t dst = st + mat * MATB + sw64(row, c);
            if (mat < 2) {
                int s = bm + row - 3 + tap;
                const __nv_bfloat16* base = (mat == 0) ? Xh : Xl;
                if (s >= 0)
                    cp16(dst, base + (size_t)s * HID + g * 128 + i0 + c * 8);
                else
                    *(uint4*)(smem + (dst - sb)) = make_uint4(0, 0, 0, 0);
            } else {
                const __nv_bfloat16* base = (mat == 2) ? Bh : Bl;
                cp16(dst, base + (size_t)(g * 128 + row) * 512 + k0 + c * 8);
            }
        }
    };

    const int nch = 16;
    load_chunk(sb, 0);         CP_COMMIT();
    load_chunk(sb + STGB, 32); CP_COMMIT();
    for (int c = 0; c < nch; ++c) {
        if (c + 1 < nch) { CP_WAIT(1); } else { CP_WAIT(0); }
        __syncthreads();
        if (c + 2 < nch) {
            load_chunk(sb + ((c + 2) % 3) * STGB, (c + 2) * 32);
            CP_COMMIT();
        }
        chunk_compute(sb + (c % 3) * STGB, lane, wm, wn, acc);
    }

    const int r0 = bm + wm * 64 + (lane >> 2);
    const int c0 = wn * 32 + (lane & 3) * 2;
#pragma unroll
    for (int mt = 0; mt < 4; ++mt)
#pragma unroll
        for (int nt = 0; nt < 4; ++nt) {
            int cl = c0 + nt * 8;
            float b0 = bias[g * 128 + cl], b1 = bias[g * 128 + cl + 1];
#pragma unroll
            for (int half = 0; half < 2; ++half) {
                int rr = r0 + mt * 16 + half * 8;
                float y0 = acc[mt][nt][half * 2 + 0] + b0;
                float y1 = acc[mt][nt][half * 2 + 1] + b1;
                y0 = y0 / (1.f + expf(-y0));
                y1 = y1 / (1.f + expf(-y1));
                *(float2*)&Y[(size_t)rr * HID + g * 128 + cl] = make_float2(y0, y1);
            }
        }
}

// ---------------- gate / beta -------------------------------------------------
__global__ __launch_bounds__(1024) void gates_kernel(const float* __restrict__ X,
        const float* __restrict__ Wg, const float* __restrict__ bg,
        const float* __restrict__ Wb, const float* __restrict__ bb,
        float* __restrict__ gate, float* __restrict__ beta) {
    __shared__ float xs[HID];
    const int s = blockIdx.x;
    for (int i = threadIdx.x; i < HID; i += 1024) xs[i] = X[(size_t)s * HID + i];
    __syncthreads();
    const int w = threadIdx.x >> 5, lane = threadIdx.x & 31;
    const float* row = (w < 16) ? (Wg + (size_t)w * HID) : (Wb + (size_t)(w - 16) * HID);
    float p = 0.f;
    for (int i = lane; i < HID; i += 32) p += xs[i] * row[i];
#pragma unroll
    for (int off = 16; off; off >>= 1) p += __shfl_xor_sync(0xffffffffu, p, off);
    if (lane == 0) {
        int hh = (w < 16) ? w : (w - 16);
        float bv = (w < 16) ? bg[hh] : bb[hh];
        float sv = 1.f / (1.f + expf(-(p + bv)));
        if (w < 16) gate[s * NHK + hh] = sv;
        else        beta[s * NHK + hh] = sv;
    }
}

// ---------------- sequential gated scan (256 CTAs, 1 col/thread) --------------
__global__ __launch_bounds__(256) void scan_kernel(const float* __restrict__ Q,
        const float* __restrict__ K, const float* __restrict__ V,
        const float* __restrict__ Beta, const float* __restrict__ Gate,
        __nv_bfloat16* __restrict__ Oh, __nv_bfloat16* __restrict__ Ol,
        float* __restrict__ Sf) {
    __shared__ float qs[32][128];
    __shared__ float ks[32][128];
    __shared__ float vs[32][16];
    __shared__ float bs[32], gs[32];
    const int h  = blockIdx.x >> 4;
    const int c0 = (blockIdx.x & 15) * 16;
    const int t  = threadIdx.x;
    const int rg = t & 15;
    const int cg = t >> 4;          // 0..15: one column each

    float S[8];
#pragma unroll
    for (int a = 0; a < 8; ++a) S[a] = 0.f;

    for (int s0 = 0; s0 < SQ; s0 += 32) {
        for (int idx = t; idx < 32 * 128; idx += 256) {
            int tt = idx >> 7, col = idx & 127;
            qs[tt][col] = Q[(size_t)(s0 + tt) * HID + h * 128 + col];
            ks[tt][col] = K[(size_t)(s0 + tt) * HID + h * 128 + col];
        }
        for (int idx = t; idx < 32 * 16; idx += 256) {
            int tt = idx >> 4, col = idx & 15;
            vs[tt][col] = V[(size_t)(s0 + tt) * NVD + h * 256 + c0 + col];
        }
        if (t < 32) {
            bs[t] = Beta[(s0 + t) * NHK + h];
            gs[t] = Gate[(s0 + t) * NHK + h];
        }
        __syncthreads();
        for (int tt = 0; tt < 32; ++tt) {
            float bt = bs[tt];
            float v  = vs[tt][cg];
            float p  = 0.f;
#pragma unroll
            for (int a = 0; a < 8; ++a) {
                float kr = ks[tt][rg + 16 * a];
                float qr = qs[tt][rg + 16 * a];
                S[a] = bt * S[a] + kr * v;
                p += qr * S[a];
            }
#pragma unroll
            for (int off = 8; off; off >>= 1)
                p += __shfl_xor_sync(0xffffffffu, p, off);
            if (rg == 0) {
                float y = gs[tt] * p;
                __nv_bfloat16 hv = __float2bfloat16(y);
                size_t oo = (size_t)(s0 + tt) * NVD + h * 256 + c0 + cg;
                Oh[oo] = hv;
                Ol[oo] = __float2bfloat16(y - __bfloat162float(hv));
            }
        }
        __syncthreads();
    }
    if (Sf != nullptr) {
#pragma unroll
        for (int a = 0; a < 8; ++a)
            Sf[(size_t)h * KDIM * VDIM + (size_t)(rg + 16 * a) * VDIM + c0 + cg] = S[a];
    }
}

// ---------------- launch ------------------------------------------------------
extern "C" void kernel_launch(void* const* d_in, const int* in_sizes, int n_in,
                              void* d_out, int out_size) {
    const float* x   = (const float*)d_in[0];
    const float* Wq  = (const float*)d_in[1];
    const float* Wk  = (const float*)d_in[2];
    const float* Wv  = (const float*)d_in[3];
    const float* Wo  = (const float*)d_in[4];
    const float* Wqc = (const float*)d_in[5];
    const float* bqc = (const float*)d_in[6];
    const float* Wkc = (const float*)d_in[7];
    const float* bkc = (const float*)d_in[8];
    const float* Wg  = (const float*)d_in[9];
    const float* bg  = (const float*)d_in[10];
    const float* Wb  = (const float*)d_in[11];
    const float* bb  = (const float*)d_in[12];
    float* out = (float*)d_out;

    float *dv, *dqc, *dkc, *dgate, *dbeta;
    cudaGetSymbolAddress((void**)&dv,    g_v);
    cudaGetSymbolAddress((void**)&dqc,   g_qc);
    cudaGetSymbolAddress((void**)&dkc,   g_kc);
    cudaGetSymbolAddress((void**)&dgate, g_gate);
    cudaGetSymbolAddress((void**)&dbeta, g_beta);

    __nv_bfloat16 *xh, *xl, *wqh, *wql, *wkh, *wkl, *wvh, *wvl, *woh, *wol, *ah, *al;
    __nv_bfloat16 *qph, *qpl, *kph, *kpl;
    cudaGetSymbolAddress((void**)&xh,  g_xh);  cudaGetSymbolAddress((void**)&xl,  g_xl);
    cudaGetSymbolAddress((void**)&wqh, g_wqh); cudaGetSymbolAddress((void**)&wql, g_wql);
    cudaGetSymbolAddress((void**)&wkh, g_wkh); cudaGetSymbolAddress((void**)&wkl, g_wkl);
    cudaGetSymbolAddress((void**)&wvh, g_wvh); cudaGetSymbolAddress((void**)&wvl, g_wvl);
    cudaGetSymbolAddress((void**)&woh, g_woh); cudaGetSymbolAddress((void**)&wol, g_wol);
    cudaGetSymbolAddress((void**)&ah,  g_ah);  cudaGetSymbolAddress((void**)&al,  g_al);
    cudaGetSymbolAddress((void**)&qph, g_qph); cudaGetSymbolAddress((void**)&qpl, g_qpl);
    cudaGetSymbolAddress((void**)&kph, g_kph); cudaGetSymbolAddress((void**)&kpl, g_kpl);

    cudaFuncSetAttribute(proj_fused, cudaFuncAttributeMaxDynamicSharedMemorySize, GSMEM);
    cudaFuncSetAttribute(gemm_mma,   cudaFuncAttributeMaxDynamicSharedMemorySize, GSMEM);
    cudaFuncSetAttribute(conv_mma,   cudaFuncAttributeMaxDynamicSharedMemorySize, GSMEM);

    dim3 blk(256);
    // 0: mega split (x, weights, conv weights reshaped)
    split_all<<<65536, blk>>>(
        (const float2*)x, (const float2*)Wq, (const float2*)Wk,
        (const float2*)Wv, (const float2*)Wo, Wqc, Wkc);
    // 1: gates
    gates_kernel<<<SQ, 1024>>>(x, Wg, bg, Wb, bb, dgate, dbeta);
    // 2: fused q/k/v projections
    proj_fused<<<1024, blk, GSMEM>>>(xh, xl, wqh, wql, wkh, wkl, wvh, wvl,
                                     qph, qpl, kph, kpl, dv);
    // 3: both convs (profiled launch)
    conv_mma<<<dim3(16, 16, 2), blk, GSMEM>>>(bqc, bkc, dqc, dkc);
    // 4: recurrent scan, 256 CTAs
    float* Sf = (out_size >= OUT_ELEMS + SF_ELEMS) ? (out + OUT_ELEMS) : nullptr;
    scan_kernel<<<256, blk>>>(dqc, dkc, dv, dbeta, dgate, ah, al, Sf);
    // 5: output projection
    gemm_mma<<<dim3(HID/128, SQ/128), blk, GSMEM>>>(ah, al, woh, wol,
        out, SQ, HID, NVD);
}

// round 14
// speedup vs baseline: 2.2331x; 1.5255x over previous
#include <cuda_runtime.h>
#include <cuda_fp16.h>
#include <math.h>
#include <cstdint>

#define SQ   2048
#define HID  2048
#define NHK  16
#define KDIM 128
#define VDIM 256
#define NVD  4096
#define OUT_ELEMS  (SQ*HID)
#define SF_ELEMS   (NHK*KDIM*VDIM)

// ---------------- scratch -----------------------------------------------------
__device__ __align__(256) float g_v   [SQ*NVD];
__device__ __align__(256) float g_qc  [SQ*HID];
__device__ __align__(256) float g_kc  [SQ*HID];
__device__ __align__(256) float g_gate[SQ*NHK];
__device__ __align__(256) float g_beta[SQ*NHK];

__device__ __align__(256) __half g_xh [SQ*HID];
__device__ __align__(256) __half g_wqh[HID*HID];
__device__ __align__(256) __half g_wkh[HID*HID];
__device__ __align__(256) __half g_wvh[NVD*HID];
__device__ __align__(256) __half g_woh[HID*NVD];
__device__ __align__(256) __half g_ah [SQ*NVD];
__device__ __align__(256) __half g_qph[SQ*HID];
__device__ __align__(256) __half g_kph[SQ*HID];
__device__ __align__(256) __half g_cqh[HID*512];
__device__ __align__(256) __half g_ckh[HID*512];

// ---------------- PTX helpers --------------------------------------------------
__device__ __forceinline__ uint32_t smem_u32(const void* p) {
    uint32_t a;
    asm("{ .reg .u64 t; cvta.to.shared.u64 t, %1; cvt.u32.u64 %0, t; }" : "=r"(a) : "l"(p));
    return a;
}
__device__ __forceinline__ void cp16(uint32_t dst, const void* src) {
    asm volatile("cp.async.cg.shared.global [%0], [%1], 16;" :: "r"(dst), "l"(src));
}
#define CP_COMMIT() asm volatile("cp.async.commit_group;")
#define CP_WAIT(n)  asm volatile("cp.async.wait_group %0;" :: "n"(n))

__device__ __forceinline__ void ldsm_x4(uint32_t& r0, uint32_t& r1, uint32_t& r2,
                                        uint32_t& r3, uint32_t a) {
    asm volatile("ldmatrix.sync.aligned.m8n8.x4.shared.b16 {%0,%1,%2,%3}, [%4];"
                 : "=r"(r0), "=r"(r1), "=r"(r2), "=r"(r3) : "r"(a));
}
__device__ __forceinline__ void mma16816(float* d, const uint32_t* a, const uint32_t* b) {
    asm volatile(
        "mma.sync.aligned.m16n8k16.row.col.f32.f16.f16.f32 "
        "{%0,%1,%2,%3},{%4,%5,%6,%7},{%8,%9},{%0,%1,%2,%3};"
        : "+f"(d[0]), "+f"(d[1]), "+f"(d[2]), "+f"(d[3])
        : "r"(a[0]), "r"(a[1]), "r"(a[2]), "r"(a[3]), "r"(b[0]), "r"(b[1]));
}

// ---------------- mega split kernel (fp32 -> fp16) ----------------------------
__device__ __forceinline__ void half_one(const float2* X, __half2* H, int i) {
    float2 x = X[i];
    __half2 h;
    h.x = __float2half_rn(x.x);
    h.y = __float2half_rn(x.y);
    H[i] = h;
}

// blocks: x 8192 | wq 8192 | wk 8192 | wv 16384 | wo 16384 | convq 4096 | convk 4096
__global__ __launch_bounds__(256) void split_all(
        const float2* x,  const float2* wq, const float2* wk,
        const float2* wv, const float2* wo,
        const float* cwq, const float* cwk) {
    int b = blockIdx.x;
    int tid = threadIdx.x;
    if (b < 8192) {
        half_one(x, (__half2*)g_xh, b * 256 + tid);
    } else if (b < 16384) {
        half_one(wq, (__half2*)g_wqh, (b - 8192) * 256 + tid);
    } else if (b < 24576) {
        half_one(wk, (__half2*)g_wkh, (b - 16384) * 256 + tid);
    } else if (b < 40960) {
        half_one(wv, (__half2*)g_wvh, (b - 24576) * 256 + tid);
    } else if (b < 57344) {
        half_one(wo, (__half2*)g_woh, (b - 40960) * 256 + tid);
    } else if (b < 61440) {
        int e = (b - 57344) * 256 + tid;
        int o = e >> 9, kk = e & 511, tap = kk >> 7, i = kk & 127;
        g_cqh[e] = __float2half_rn(cwq[o * 512 + i * 4 + tap]);
    } else {
        int e = (b - 61440) * 256 + tid;
        int o = e >> 9, kk = e & 511, tap = kk >> 7, i = kk & 127;
        g_ckh[e] = __float2half_rn(cwk[o * 512 + i * 4 + tap]);
    }
}

// ---------------- common GEMM pieces ------------------------------------------
// 64B rows with XOR swizzle; stage = A(8KB) + B(8KB); 3 stages, 2 CTAs/SM.
#define MATB  8192u
#define STGB  (2u*MATB)      // 16384
#define GSMEM (3u*STGB)      // 49152

__device__ __forceinline__ uint32_t sw64(uint32_t row, uint32_t c) {
    return row * 64u + ((c ^ ((row >> 1) & 3u)) << 4);
}

__device__ __forceinline__ void ld_stage(uint32_t st,
        const __half* __restrict__ A, const __half* __restrict__ B,
        int bm, int bn, int k0, int K, int t) {
#pragma unroll
    for (int i = 0; i < 4; ++i) {
        int idx = t + i * 256;          // 0..1023
        int mat = idx >> 9;             // 0:A 1:B
        int j   = idx & 511;
        int row = j >> 2, c = j & 3;
        const __half* base = mat ? B : A;
        int grow = (mat ? bn : bm) + row;
        cp16(st + mat * MATB + sw64(row, c),
             base + (size_t)grow * K + k0 + c * 8);
    }
}

// one K=32 chunk, single-pass fp16
__device__ __forceinline__ void chunk_compute(uint32_t stg, int lane, int wm, int wn,
                                              float acc[4][4][4]) {
    const uint32_t rA0 = (uint32_t)wm * 64 + (lane & 15);
    const uint32_t hiA = (uint32_t)lane >> 4;
    const uint32_t sA  = (rA0 >> 1) & 3u;
    const uint32_t rB0 = (uint32_t)wn * 32 + (((uint32_t)lane >> 4) << 3) + (lane & 7);
    const uint32_t hB  = ((uint32_t)lane >> 3) & 1u;
    const uint32_t sB  = (rB0 >> 1) & 3u;
    const uint32_t baseA = stg + rA0 * 64;
    const uint32_t baseB = stg + MATB + rB0 * 64;
#pragma unroll
    for (int kh = 0; kh < 2; ++kh) {
        const uint32_t cA = (((uint32_t)(kh * 2) + hiA) ^ sA) << 4;
        const uint32_t cB = (((uint32_t)(kh * 2) + hB) ^ sB) << 4;
        uint32_t a[4][4], b[4][2];
#pragma unroll
        for (int mt = 0; mt < 4; ++mt)
            ldsm_x4(a[mt][0], a[mt][1], a[mt][2], a[mt][3],
                    baseA + mt * 1024 + cA);
#pragma unroll
        for (int p = 0; p < 2; ++p)
            ldsm_x4(b[2*p][0], b[2*p][1], b[2*p+1][0], b[2*p+1][1],
                    baseB + p * 1024 + cB);
#pragma unroll
        for (int mt = 0; mt < 4; ++mt)
#pragma unroll
            for (int nt = 0; nt < 4; ++nt)
                mma16816(acc[mt][nt], a[mt], b[nt]);
    }
}

// ---------------- fused q/k/v projection --------------------------------------
__global__ __launch_bounds__(256, 2) void proj_fused(
        __half* __restrict__ Qp, __half* __restrict__ Kp, float* __restrict__ V) {
    extern __shared__ char smem[];
    uint32_t sb = smem_u32(smem);
    const int t = threadIdx.x, wid = t >> 5, lane = t & 31;
    const int wm = wid >> 2, wn = wid & 3;

    int bx = blockIdx.x;
    int which, bm, bn;
    const __half* B_;
    if (bx < 256)      { which = 0; bm = (bx >> 4) << 7;          bn = (bx & 15) << 7; B_ = g_wqh; }
    else if (bx < 512) { which = 1; int i = bx - 256; bm = (i >> 4) << 7; bn = (i & 15) << 7; B_ = g_wkh; }
    else               { which = 2; int i = bx - 512; bm = (i >> 5) << 7; bn = (i & 31) << 7; B_ = g_wvh; }

    float acc[4][4][4];
#pragma unroll
    for (int mt = 0; mt < 4; ++mt)
#pragma unroll
        for (int nt = 0; nt < 4; ++nt)
#pragma unroll
            for (int r = 0; r < 4; ++r) acc[mt][nt][r] = 0.f;

    const int nch = HID / 32;   // 64
    ld_stage(sb,        g_xh, B_, bm, bn, 0,  HID, t); CP_COMMIT();
    ld_stage(sb + STGB, g_xh, B_, bm, bn, 32, HID, t); CP_COMMIT();
    for (int c = 0; c < nch; ++c) {
        if (c + 1 < nch) { CP_WAIT(1); } else { CP_WAIT(0); }
        __syncthreads();
        if (c + 2 < nch) {
            ld_stage(sb + ((c + 2) % 3) * STGB, g_xh, B_, bm, bn, (c + 2) * 32, HID, t);
            CP_COMMIT();
        }
        chunk_compute(sb + (c % 3) * STGB, lane, wm, wn, acc);
    }

    const int r0 = bm + wm * 64 + (lane >> 2);
    const int ccl = wn * 32 + (lane & 3) * 2;
    if (which < 2) {
        __half* Ch = which ? Kp : Qp;
#pragma unroll
        for (int mt = 0; mt < 4; ++mt)
#pragma unroll
            for (int nt = 0; nt < 4; ++nt)
#pragma unroll
                for (int half = 0; half < 2; ++half) {
                    int rr = r0 + mt * 16 + half * 8;
                    int cl = bn + ccl + nt * 8;
                    __half2 h;
                    h.x = __float2half_rn(acc[mt][nt][half * 2 + 0]);
                    h.y = __float2half_rn(acc[mt][nt][half * 2 + 1]);
                    ((__half2*)Ch)[((size_t)rr * HID + cl) >> 1] = h;
                }
    } else {
#pragma unroll
        for (int mt = 0; mt < 4; ++mt)
#pragma unroll
            for (int nt = 0; nt < 4; ++nt) {
                int rr = r0 + mt * 16;
                int cl = bn + ccl + nt * 8;
                *(float2*)&V[(size_t)rr * NVD + cl]       = make_float2(acc[mt][nt][0], acc[mt][nt][1]);
                *(float2*)&V[(size_t)(rr + 8) * NVD + cl] = make_float2(acc[mt][nt][2], acc[mt][nt][3]);
            }
    }
}

// ---------------- output projection -------------------------------------------
__global__ __launch_bounds__(256, 2) void gemm_mma(
        const __half* __restrict__ A, const __half* __restrict__ B,
        float* __restrict__ C, int M, int N, int K) {
    extern __shared__ char smem[];
    uint32_t sb = smem_u32(smem);
    const int t = threadIdx.x, wid = t >> 5, lane = t & 31;
    const int wm = wid >> 2, wn = wid & 3;
    const int bm = blockIdx.y * 128, bn = blockIdx.x * 128;

    float acc[4][4][4];
#pragma unroll
    for (int mt = 0; mt < 4; ++mt)
#pragma unroll
        for (int nt = 0; nt < 4; ++nt)
#pragma unroll
            for (int r = 0; r < 4; ++r) acc[mt][nt][r] = 0.f;

    const int nch = K / 32;
    ld_stage(sb,        A, B, bm, bn, 0,  K, t); CP_COMMIT();
    ld_stage(sb + STGB, A, B, bm, bn, 32, K, t); CP_COMMIT();
    for (int c = 0; c < nch; ++c) {
        if (c + 1 < nch) { CP_WAIT(1); } else { CP_WAIT(0); }
        __syncthreads();
        if (c + 2 < nch) {
            ld_stage(sb + ((c + 2) % 3) * STGB, A, B, bm, bn, (c + 2) * 32, K, t);
            CP_COMMIT();
        }
        chunk_compute(sb + (c % 3) * STGB, lane, wm, wn, acc);
    }

    const int r0 = bm + wm * 64 + (lane >> 2);
    const int cc = bn + wn * 32 + (lane & 3) * 2;
#pragma unroll
    for (int mt = 0; mt < 4; ++mt)
#pragma unroll
        for (int nt = 0; nt < 4; ++nt) {
            int rr = r0 + mt * 16;
            int cl = cc + nt * 8;
            *(float2*)&C[(size_t)rr * N + cl]       = make_float2(acc[mt][nt][0], acc[mt][nt][1]);
            *(float2*)&C[(size_t)(rr + 8) * N + cl] = make_float2(acc[mt][nt][2], acc[mt][nt][3]);
        }
}

// ---------------- conv via fp16 mma -------------------------------------------
__global__ __launch_bounds__(256, 2) void conv_mma(
        const float* __restrict__ bq, const float* __restrict__ bk,
        float* __restrict__ Yq, float* __restrict__ Yk) {
    extern __shared__ char smem[];
    uint32_t sb = smem_u32(smem);
    const int t = threadIdx.x, wid = t >> 5, lane = t & 31;
    const int wm = wid >> 2, wn = wid & 3;
    const int g  = blockIdx.x;
    const int bm = blockIdx.y * 128;
    const int cz = blockIdx.z;
    const __half* X = cz ? g_kph : g_qph;
    const __half* B = cz ? g_ckh : g_cqh;
    const float* bias = cz ? bk : bq;
    float* Y = cz ? Yk : Yq;

    float acc[4][4][4];
#pragma unroll
    for (int mt = 0; mt < 4; ++mt)
#pragma unroll
        for (int nt = 0; nt < 4; ++nt)
#pragma unroll
            for (int r = 0; r < 4; ++r) acc[mt][nt][r] = 0.f;

    auto load_chunk = [&](uint32_t st, int k0) {
        int tap = k0 >> 7, i0 = k0 & 127;
#pragma unroll
        for (int i = 0; i < 4; ++i) {
            int idx = t + i * 256;
            int mat = idx >> 9;
            int j   = idx & 511;
            int row = j >> 2, c = j & 3;
            uint32_t dst = st + mat * MATB + sw64(row, c);
            if (mat == 0) {
                int s = bm + row - 3 + tap;
                if (s >= 0)
                    cp16(dst, X + (size_t)s * HID + g * 128 + i0 + c * 8);
                else
                    *(uint4*)(smem + (dst - sb)) = make_uint4(0, 0, 0, 0);
            } else {
                cp16(dst, B + (size_t)(g * 128 + row) * 512 + k0 + c * 8);
            }
        }
    };

    const int nch = 16;
    load_chunk(sb, 0);         CP_COMMIT();
    load_chunk(sb + STGB, 32); CP_COMMIT();
    for (int c = 0; c < nch; ++c) {
        if (c + 1 < nch) { CP_WAIT(1); } else { CP_WAIT(0); }
        __syncthreads();
        if (c + 2 < nch) {
            load_chunk(sb + ((c + 2) % 3) * STGB, (c + 2) * 32);
            CP_COMMIT();
        }
        chunk_compute(sb + (c % 3) * STGB, lane, wm, wn, acc);
    }

    const int r0 = bm + wm * 64 + (lane >> 2);
    const int c0 = wn * 32 + (lane & 3) * 2;
#pragma unroll
    for (int mt = 0; mt < 4; ++mt)
#pragma unroll
        for (int nt = 0; nt < 4; ++nt) {
            int cl = c0 + nt * 8;
            float b0 = bias[g * 128 + cl], b1 = bias[g * 128 + cl + 1];
#pragma unroll
            for (int half = 0; half < 2; ++half) {
                int rr = r0 + mt * 16 + half * 8;
                float y0 = acc[mt][nt][half * 2 + 0] + b0;
                float y1 = acc[mt][nt][half * 2 + 1] + b1;
                y0 = y0 / (1.f + expf(-y0));
                y1 = y1 / (1.f + expf(-y1));
                *(float2*)&Y[(size_t)rr * HID + g * 128 + cl] = make_float2(y0, y1);
            }
        }
}

// ---------------- gate / beta -------------------------------------------------
__global__ __launch_bounds__(1024) void gates_kernel(const float* __restrict__ X,
        const float* __restrict__ Wg, const float* __restrict__ bg,
        const float* __restrict__ Wb, const float* __restrict__ bb,
        float* __restrict__ gate, float* __restrict__ beta) {
    __shared__ float xs[HID];
    const int s = blockIdx.x;
    for (int i = threadIdx.x; i < HID; i += 1024) xs[i] = X[(size_t)s * HID + i];
    __syncthreads();
    const int w = threadIdx.x >> 5, lane = threadIdx.x & 31;
    const float* row = (w < 16) ? (Wg + (size_t)w * HID) : (Wb + (size_t)(w - 16) * HID);
    float p = 0.f;
    for (int i = lane; i < HID; i += 32) p += xs[i] * row[i];
#pragma unroll
    for (int off = 16; off; off >>= 1) p += __shfl_xor_sync(0xffffffffu, p, off);
    if (lane == 0) {
        int hh = (w < 16) ? w : (w - 16);
        float bv = (w < 16) ? bg[hh] : bb[hh];
        float sv = 1.f / (1.f + expf(-(p + bv)));
        if (w < 16) gate[s * NHK + hh] = sv;
        else        beta[s * NHK + hh] = sv;
    }
}

// ---------------- sequential gated scan (fp16 output) -------------------------
__global__ __launch_bounds__(256) void scan_kernel(const float* __restrict__ Q,
        const float* __restrict__ K, const float* __restrict__ V,
        const float* __restrict__ Beta, const float* __restrict__ Gate,
        __half* __restrict__ O, float* __restrict__ Sf) {
    __shared__ float qs[32][128];
    __shared__ float ks[32][128];
    __shared__ float vs[32][32];
    __shared__ float bs[32], gs[32];
    const int h  = blockIdx.x >> 3;
    const int c0 = (blockIdx.x & 7) * 32;
    const int t  = threadIdx.x;
    const int rg = t & 15;
    const int cg = t >> 4;

    float S0[8], S1[8];
#pragma unroll
    for (int a = 0; a < 8; ++a) { S0[a] = 0.f; S1[a] = 0.f; }

    for (int s0 = 0; s0 < SQ; s0 += 32) {
        for (int idx = t; idx < 32 * 128; idx += 256) {
            int tt = idx >> 7, col = idx & 127;
            qs[tt][col] = Q[(size_t)(s0 + tt) * HID + h * 128 + col];
            ks[tt][col] = K[(size_t)(s0 + tt) * HID + h * 128 + col];
        }
        for (int idx = t; idx < 32 * 32; idx += 256) {
            int tt = idx >> 5, col = idx & 31;
            vs[tt][col] = V[(size_t)(s0 + tt) * NVD + h * 256 + c0 + col];
        }
        if (t < 32) {
            bs[t] = Beta[(s0 + t) * NHK + h];
            gs[t] = Gate[(s0 + t) * NHK + h];
        }
        __syncthreads();
        for (int tt = 0; tt < 32; ++tt) {
            float bt = bs[tt];
            float v0 = vs[tt][cg * 2 + 0];
            float v1 = vs[tt][cg * 2 + 1];
            float p0 = 0.f, p1 = 0.f;
#pragma unroll
            for (int a = 0; a < 8; ++a) {
                float kr = ks[tt][rg + 16 * a];
                float qr = qs[tt][rg + 16 * a];
                S0[a] = bt * S0[a] + kr * v0;
                S1[a] = bt * S1[a] + kr * v1;
                p0 += qr * S0[a];
                p1 += qr * S1[a];
            }
#pragma unroll
            for (int off = 8; off; off >>= 1) {
                p0 += __shfl_xor_sync(0xffffffffu, p0, off);
                p1 += __shfl_xor_sync(0xffffffffu, p1, off);
            }
            if (rg == 0) {
                float gt = gs[tt];
                __half2 hv;
                hv.x = __float2half_rn(gt * p0);
                hv.y = __float2half_rn(gt * p1);
                ((__half2*)O)[((size_t)(s0 + tt) * NVD + h * 256 + c0 + cg * 2) >> 1] = hv;
            }
        }
        __syncthreads();
    }
    if (Sf != nullptr) {
#pragma unroll
        for (int a = 0; a < 8; ++a) {
            size_t base = (size_t)h * KDIM * VDIM + (size_t)(rg + 16 * a) * VDIM
                        + c0 + cg * 2;
            Sf[base]     = S0[a];
            Sf[base + 1] = S1[a];
        }
    }
}

// ---------------- launch ------------------------------------------------------
extern "C" void kernel_launch(void* const* d_in, const int* in_sizes, int n_in,
                              void* d_out, int out_size) {
    const float* x   = (const float*)d_in[0];
    const float* Wq  = (const float*)d_in[1];
    const float* Wk  = (const float*)d_in[2];
    const float* Wv  = (const float*)d_in[3];
    const float* Wo  = (const float*)d_in[4];
    const float* Wqc = (const float*)d_in[5];
    const float* bqc = (const float*)d_in[6];
    const float* Wkc = (const float*)d_in[7];
    const float* bkc = (const float*)d_in[8];
    const float* Wg  = (const float*)d_in[9];
    const float* bg  = (const float*)d_in[10];
    const float* Wb  = (const float*)d_in[11];
    const float* bb  = (const float*)d_in[12];
    float* out = (float*)d_out;

    float *dv, *dqc, *dkc, *dgate, *dbeta;
    cudaGetSymbolAddress((void**)&dv,    g_v);
    cudaGetSymbolAddress((void**)&dqc,   g_qc);
    cudaGetSymbolAddress((void**)&dkc,   g_kc);
    cudaGetSymbolAddress((void**)&dgate, g_gate);
    cudaGetSymbolAddress((void**)&dbeta, g_beta);

    __half *ah, *woh, *qph, *kph;
    cudaGetSymbolAddress((void**)&ah,  g_ah);
    cudaGetSymbolAddress((void**)&woh, g_woh);
    cudaGetSymbolAddress((void**)&qph, g_qph);
    cudaGetSymbolAddress((void**)&kph, g_kph);

    cudaFuncSetAttribute(proj_fused, cudaFuncAttributeMaxDynamicSharedMemorySize, GSMEM);
    cudaFuncSetAttribute(gemm_mma,   cudaFuncAttributeMaxDynamicSharedMemorySize, GSMEM);
    cudaFuncSetAttribute(conv_mma,   cudaFuncAttributeMaxDynamicSharedMemorySize, GSMEM);

    dim3 blk(256);
    // 0: mega split (x, weights, conv weights reshaped), all -> fp16
    split_all<<<65536, blk>>>(
        (const float2*)x, (const float2*)Wq, (const float2*)Wk,
        (const float2*)Wv, (const float2*)Wo, Wqc, Wkc);
    // 1: gates
    gates_kernel<<<SQ, 1024>>>(x, Wg, bg, Wb, bb, dgate, dbeta);
    // 2: fused q/k/v projections
    proj_fused<<<1024, blk, GSMEM>>>(qph, kph, dv);
    // 3: both convs
    conv_mma<<<dim3(16, 16, 2), blk, GSMEM>>>(bqc, bkc, dqc, dkc);
    // 4: recurrent scan
    float* Sf = (out_size >= OUT_ELEMS + SF_ELEMS) ? (out + OUT_ELEMS) : nullptr;
    scan_kernel<<<128, blk>>>(dqc, dkc, dv, dbeta, dgate, ah, Sf);
    // 5: output projection
    gemm_mma<<<dim3(HID/128, SQ/128), blk, GSMEM>>>(ah, woh, out, SQ, HID, NVD);
}

// round 16
// speedup vs baseline: 2.6136x; 1.1704x over previous
#include <cuda_runtime.h>
#include <cuda_fp16.h>
#include <math.h>
#include <cstdint>

#define SQ   2048
#define HID  2048
#define NHK  16
#define KDIM 128
#define VDIM 256
#define NVD  4096
#define OUT_ELEMS  (SQ*HID)
#define SF_ELEMS   (NHK*KDIM*VDIM)

// ---------------- scratch -----------------------------------------------------
__device__ __align__(256) float g_v   [SQ*NVD];
__device__ __align__(256) float g_qc  [SQ*HID];
__device__ __align__(256) float g_kc  [SQ*HID];
__device__ __align__(256) float g_gate[SQ*NHK];
__device__ __align__(256) float g_beta[SQ*NHK];
__device__ __align__(256) float g_part[2*SQ*NVD];   // partial scan outputs

__device__ __align__(256) __half g_xh [SQ*HID];
__device__ __align__(256) __half g_wqh[HID*HID];
__device__ __align__(256) __half g_wkh[HID*HID];
__device__ __align__(256) __half g_wvh[NVD*HID];
__device__ __align__(256) __half g_woh[HID*NVD];
__device__ __align__(256) __half g_ah [SQ*NVD];
__device__ __align__(256) __half g_qph[SQ*HID];
__device__ __align__(256) __half g_kph[SQ*HID];
__device__ __align__(256) __half g_cqh[HID*512];
__device__ __align__(256) __half g_ckh[HID*512];

// ---------------- PTX helpers --------------------------------------------------
__device__ __forceinline__ uint32_t smem_u32(const void* p) {
    uint32_t a;
    asm("{ .reg .u64 t; cvta.to.shared.u64 t, %1; cvt.u32.u64 %0, t; }" : "=r"(a) : "l"(p));
    return a;
}
__device__ __forceinline__ void cp16(uint32_t dst, const void* src) {
    asm volatile("cp.async.cg.shared.global [%0], [%1], 16;" :: "r"(dst), "l"(src));
}
#define CP_COMMIT() asm volatile("cp.async.commit_group;")
#define CP_WAIT(n)  asm volatile("cp.async.wait_group %0;" :: "n"(n))

__device__ __forceinline__ void ldsm_x4(uint32_t& r0, uint32_t& r1, uint32_t& r2,
                                        uint32_t& r3, uint32_t a) {
    asm volatile("ldmatrix.sync.aligned.m8n8.x4.shared.b16 {%0,%1,%2,%3}, [%4];"
                 : "=r"(r0), "=r"(r1), "=r"(r2), "=r"(r3) : "r"(a));
}
__device__ __forceinline__ void mma16816(float* d, const uint32_t* a, const uint32_t* b) {
    asm volatile(
        "mma.sync.aligned.m16n8k16.row.col.f32.f16.f16.f32 "
        "{%0,%1,%2,%3},{%4,%5,%6,%7},{%8,%9},{%0,%1,%2,%3};"
        : "+f"(d[0]), "+f"(d[1]), "+f"(d[2]), "+f"(d[3])
        : "r"(a[0]), "r"(a[1]), "r"(a[2]), "r"(a[3]), "r"(b[0]), "r"(b[1]));
}

// ---------------- mega split + gates kernel -----------------------------------
__device__ __forceinline__ void half_one(const float2* X, __half2* H, int i) {
    float2 x = X[i];
    __half2 h;
    h.x = __float2half_rn(x.x);
    h.y = __float2half_rn(x.y);
    H[i] = h;
}

// blocks: x 8192 | wq 8192 | wk 8192 | wv 16384 | wo 16384 | convq 4096 |
//         convk 4096 | gates 2048  (total 67584)
__global__ __launch_bounds__(256) void split_all(
        const float* xf, const float2* wq, const float2* wk,
        const float2* wv, const float2* wo,
        const float* cwq, const float* cwk,
        const float* Wg, const float* bg, const float* Wb, const float* bb,
        float* gate, float* beta) {
    __shared__ float xs[HID];
    int b = blockIdx.x;
    int tid = threadIdx.x;
    if (b < 8192) {
        half_one((const float2*)xf, (__half2*)g_xh, b * 256 + tid);
    } else if (b < 16384) {
        half_one(wq, (__half2*)g_wqh, (b - 8192) * 256 + tid);
    } else if (b < 24576) {
        half_one(wk, (__half2*)g_wkh, (b - 16384) * 256 + tid);
    } else if (b < 40960) {
        half_one(wv, (__half2*)g_wvh, (b - 24576) * 256 + tid);
    } else if (b < 57344) {
        half_one(wo, (__half2*)g_woh, (b - 40960) * 256 + tid);
    } else if (b < 61440) {
        int e = (b - 57344) * 256 + tid;
        int o = e >> 9, kk = e & 511, tap = kk >> 7, i = kk & 127;
        g_cqh[e] = __float2half_rn(cwq[o * 512 + i * 4 + tap]);
    } else if (b < 65536) {
        int e = (b - 61440) * 256 + tid;
        int o = e >> 9, kk = e & 511, tap = kk >> 7, i = kk & 127;
        g_ckh[e] = __float2half_rn(cwk[o * 512 + i * 4 + tap]);
    } else {
        int s = b - 65536;
        for (int i = tid; i < HID; i += 256) xs[i] = xf[(size_t)s * HID + i];
        __syncthreads();
        int w = tid >> 5, lane = tid & 31;
#pragma unroll
        for (int j = 0; j < 4; ++j) {
            int r = w * 4 + j;
            const float* row = (r < 16) ? (Wg + (size_t)r * HID)
                                        : (Wb + (size_t)(r - 16) * HID);
            float p = 0.f;
            for (int i = lane; i < HID; i += 32) p += xs[i] * row[i];
#pragma unroll
            for (int off = 16; off; off >>= 1) p += __shfl_xor_sync(0xffffffffu, p, off);
            if (lane == 0) {
                float bv = (r < 16) ? bg[r] : bb[r - 16];
                float sv = 1.f / (1.f + expf(-(p + bv)));
                if (r < 16) gate[s * NHK + r] = sv;
                else        beta[s * NHK + r - 16] = sv;
            }
        }
    }
}

// ---------------- common GEMM pieces ------------------------------------------
#define MATB  8192u
#define STGB  (2u*MATB)      // 16384
#define GSMEM (3u*STGB)      // 49152

__device__ __forceinline__ uint32_t sw64(uint32_t row, uint32_t c) {
    return row * 64u + ((c ^ ((row >> 1) & 3u)) << 4);
}

__device__ __forceinline__ void ld_stage(uint32_t st,
        const __half* __restrict__ A, const __half* __restrict__ B,
        int bm, int bn, int k0, int K, int t) {
#pragma unroll
    for (int i = 0; i < 4; ++i) {
        int idx = t + i * 256;
        int mat = idx >> 9;
        int j   = idx & 511;
        int row = j >> 2, c = j & 3;
        const __half* base = mat ? B : A;
        int grow = (mat ? bn : bm) + row;
        cp16(st + mat * MATB + sw64(row, c),
             base + (size_t)grow * K + k0 + c * 8);
    }
}

__device__ __forceinline__ void chunk_compute(uint32_t stg, int lane, int wm, int wn,
                                              float acc[4][4][4]) {
    const uint32_t rA0 = (uint32_t)wm * 64 + (lane & 15);
    const uint32_t hiA = (uint32_t)lane >> 4;
    const uint32_t sA  = (rA0 >> 1) & 3u;
    const uint32_t rB0 = (uint32_t)wn * 32 + (((uint32_t)lane >> 4) << 3) + (lane & 7);
    const uint32_t hB  = ((uint32_t)lane >> 3) & 1u;
    const uint32_t sB  = (rB0 >> 1) & 3u;
    const uint32_t baseA = stg + rA0 * 64;
    const uint32_t baseB = stg + MATB + rB0 * 64;
#pragma unroll
    for (int kh = 0; kh < 2; ++kh) {
        const uint32_t cA = (((uint32_t)(kh * 2) + hiA) ^ sA) << 4;
        const uint32_t cB = (((uint32_t)(kh * 2) + hB) ^ sB) << 4;
        uint32_t a[4][4], b[4][2];
#pragma unroll
        for (int mt = 0; mt < 4; ++mt)
            ldsm_x4(a[mt][0], a[mt][1], a[mt][2], a[mt][3],
                    baseA + mt * 1024 + cA);
#pragma unroll
        for (int p = 0; p < 2; ++p)
            ldsm_x4(b[2*p][0], b[2*p][1], b[2*p+1][0], b[2*p+1][1],
                    baseB + p * 1024 + cB);
#pragma unroll
        for (int mt = 0; mt < 4; ++mt)
#pragma unroll
            for (int nt = 0; nt < 4; ++nt)
                mma16816(acc[mt][nt], a[mt], b[nt]);
    }
}

// ---------------- fused q/k/v projection --------------------------------------
__global__ __launch_bounds__(256, 2) void proj_fused(
        __half* __restrict__ Qp, __half* __restrict__ Kp, float* __restrict__ V) {
    extern __shared__ char smem[];
    uint32_t sb = smem_u32(smem);
    const int t = threadIdx.x, wid = t >> 5, lane = t & 31;
    const int wm = wid >> 2, wn = wid & 3;

    int bx = blockIdx.x;
    int which, bm, bn;
    const __half* B_;
    if (bx < 256)      { which = 0; bm = (bx >> 4) << 7;          bn = (bx & 15) << 7; B_ = g_wqh; }
    else if (bx < 512) { which = 1; int i = bx - 256; bm = (i >> 4) << 7; bn = (i & 15) << 7; B_ = g_wkh; }
    else               { which = 2; int i = bx - 512; bm = (i >> 5) << 7; bn = (i & 31) << 7; B_ = g_wvh; }

    float acc[4][4][4];
#pragma unroll
    for (int mt = 0; mt < 4; ++mt)
#pragma unroll
        for (int nt = 0; nt < 4; ++nt)
#pragma unroll
            for (int r = 0; r < 4; ++r) acc[mt][nt][r] = 0.f;

    const int nch = HID / 32;
    ld_stage(sb,        g_xh, B_, bm, bn, 0,  HID, t); CP_COMMIT();
    ld_stage(sb + STGB, g_xh, B_, bm, bn, 32, HID, t); CP_COMMIT();
    for (int c = 0; c < nch; ++c) {
        if (c + 1 < nch) { CP_WAIT(1); } else { CP_WAIT(0); }
        __syncthreads();
        if (c + 2 < nch) {
            ld_stage(sb + ((c + 2) % 3) * STGB, g_xh, B_, bm, bn, (c + 2) * 32, HID, t);
            CP_COMMIT();
        }
        chunk_compute(sb + (c % 3) * STGB, lane, wm, wn, acc);
    }

    const int r0 = bm + wm * 64 + (lane >> 2);
    const int ccl = wn * 32 + (lane & 3) * 2;
    if (which < 2) {
        __half* Ch = which ? Kp : Qp;
#pragma unroll
        for (int mt = 0; mt < 4; ++mt)
#pragma unroll
            for (int nt = 0; nt < 4; ++nt)
#pragma unroll
                for (int half = 0; half < 2; ++half) {
                    int rr = r0 + mt * 16 + half * 8;
                    int cl = bn + ccl + nt * 8;
                    __half2 h;
                    h.x = __float2half_rn(acc[mt][nt][half * 2 + 0]);
                    h.y = __float2half_rn(acc[mt][nt][half * 2 + 1]);
                    ((__half2*)Ch)[((size_t)rr * HID + cl) >> 1] = h;
                }
    } else {
#pragma unroll
        for (int mt = 0; mt < 4; ++mt)
#pragma unroll
            for (int nt = 0; nt < 4; ++nt) {
                int rr = r0 + mt * 16;
                int cl = bn + ccl + nt * 8;
                *(float2*)&V[(size_t)rr * NVD + cl]       = make_float2(acc[mt][nt][0], acc[mt][nt][1]);
                *(float2*)&V[(size_t)(rr + 8) * NVD + cl] = make_float2(acc[mt][nt][2], acc[mt][nt][3]);
            }
    }
}

// ---------------- output projection -------------------------------------------
__global__ __launch_bounds__(256, 2) void gemm_mma(
        const __half* __restrict__ A, const __half* __restrict__ B,
        float* __restrict__ C, int M, int N, int K) {
    extern __shared__ char smem[];
    uint32_t sb = smem_u32(smem);
    const int t = threadIdx.x, wid = t >> 5, lane = t & 31;
    const int wm = wid >> 2, wn = wid & 3;
    const int bm = blockIdx.y * 128, bn = blockIdx.x * 128;

    float acc[4][4][4];
#pragma unroll
    for (int mt = 0; mt < 4; ++mt)
#pragma unroll
        for (int nt = 0; nt < 4; ++nt)
#pragma unroll
            for (int r = 0; r < 4; ++r) acc[mt][nt][r] = 0.f;

    const int nch = K / 32;
    ld_stage(sb,        A, B, bm, bn, 0,  K, t); CP_COMMIT();
    ld_stage(sb + STGB, A, B, bm, bn, 32, K, t); CP_COMMIT();
    for (int c = 0; c < nch; ++c) {
        if (c + 1 < nch) { CP_WAIT(1); } else { CP_WAIT(0); }
        __syncthreads();
        if (c + 2 < nch) {
            ld_stage(sb + ((c + 2) % 3) * STGB, A, B, bm, bn, (c + 2) * 32, K, t);
            CP_COMMIT();
        }
        chunk_compute(sb + (c % 3) * STGB, lane, wm, wn, acc);
    }

    const int r0 = bm + wm * 64 + (lane >> 2);
    const int cc = bn + wn * 32 + (lane & 3) * 2;
#pragma unroll
    for (int mt = 0; mt < 4; ++mt)
#pragma unroll
        for (int nt = 0; nt < 4; ++nt) {
            int rr = r0 + mt * 16;
            int cl = cc + nt * 8;
            *(float2*)&C[(size_t)rr * N + cl]       = make_float2(acc[mt][nt][0], acc[mt][nt][1]);
            *(float2*)&C[(size_t)(rr + 8) * N + cl] = make_float2(acc[mt][nt][2], acc[mt][nt][3]);
        }
}

// ---------------- conv via fp16 mma -------------------------------------------
__global__ __launch_bounds__(256, 2) void conv_mma(
        const float* __restrict__ bq, const float* __restrict__ bk,
        float* __restrict__ Yq, float* __restrict__ Yk) {
    extern __shared__ char smem[];
    uint32_t sb = smem_u32(smem);
    const int t = threadIdx.x, wid = t >> 5, lane = t & 31;
    const int wm = wid >> 2, wn = wid & 3;
    const int g  = blockIdx.x;
    const int bm = blockIdx.y * 128;
    const int cz = blockIdx.z;
    const __half* X = cz ? g_kph : g_qph;
    const __half* B = cz ? g_ckh : g_cqh;
    const float* bias = cz ? bk : bq;
    float* Y = cz ? Yk : Yq;

    float acc[4][4][4];
#pragma unroll
    for (int mt = 0; mt < 4; ++mt)
#pragma unroll
        for (int nt = 0; nt < 4; ++nt)
#pragma unroll
            for (int r = 0; r < 4; ++r) acc[mt][nt][r] = 0.f;

    auto load_chunk = [&](uint32_t st, int k0) {
        int tap = k0 >> 7, i0 = k0 & 127;
#pragma unroll
        for (int i = 0; i < 4; ++i) {
            int idx = t + i * 256;
            int mat = idx >> 9;
            int j   = idx & 511;
            int row = j >> 2, c = j & 3;
            uint32_t dst = st + mat * MATB + sw64(row, c);
            if (mat == 0) {
                int s = bm + row - 3 + tap;
                if (s >= 0)
                    cp16(dst, X + (size_t)s * HID + g * 128 + i0 + c * 8);
                else
                    *(uint4*)(smem + (dst - sb)) = make_uint4(0, 0, 0, 0);
            } else {
                cp16(dst, B + (size_t)(g * 128 + row) * 512 + k0 + c * 8);
            }
        }
    };

    const int nch = 16;
    load_chunk(sb, 0);         CP_COMMIT();
    load_chunk(sb + STGB, 32); CP_COMMIT();
    for (int c = 0; c < nch; ++c) {
        if (c + 1 < nch) { CP_WAIT(1); } else { CP_WAIT(0); }
        __syncthreads();
        if (c + 2 < nch) {
            load_chunk(sb + ((c + 2) % 3) * STGB, (c + 2) * 32);
            CP_COMMIT();
        }
        chunk_compute(sb + (c % 3) * STGB, lane, wm, wn, acc);
    }

    const int r0 = bm + wm * 64 + (lane >> 2);
    const int c0 = wn * 32 + (lane & 3) * 2;
#pragma unroll
    for (int mt = 0; mt < 4; ++mt)
#pragma unroll
        for (int nt = 0; nt < 4; ++nt) {
            int cl = c0 + nt * 8;
            float b0 = bias[g * 128 + cl], b1 = bias[g * 128 + cl + 1];
#pragma unroll
            for (int half = 0; half < 2; ++half) {
                int rr = r0 + mt * 16 + half * 8;
                float y0 = acc[mt][nt][half * 2 + 0] + b0;
                float y1 = acc[mt][nt][half * 2 + 1] + b1;
                y0 = y0 / (1.f + expf(-y0));
                y1 = y1 / (1.f + expf(-y1));
                *(float2*)&Y[(size_t)rr * HID + g * 128 + cl] = make_float2(y0, y1);
            }
        }
}

// ---------------- row-split gated scan ----------------------------------------
// 256 CTAs: h (16) x row-half rh (2) x col-group (8 of 32 cols).
// Thread (rg=t&7, cg=t>>3) owns rows rh*64 + rg + 8a (a<8), column c0+cg.
// Writes PARTIAL dot products to g_part[rh]; combine_kernel sums + gates.
__global__ __launch_bounds__(256) void scan_kernel(const float* __restrict__ Q,
        const float* __restrict__ K, const float* __restrict__ V,
        const float* __restrict__ Beta, float* __restrict__ P,
        float* __restrict__ Sf) {
    __shared__ float qs[32][64];
    __shared__ float ks[32][64];
    __shared__ float vs[32][32];
    __shared__ float bs[32];
    const int h  = blockIdx.x >> 4;
    const int rh = (blockIdx.x >> 3) & 1;
    const int c0 = (blockIdx.x & 7) * 32;
    const int t  = threadIdx.x;
    const int rg = t & 7;
    const int cg = t >> 3;

    float S[8];
#pragma unroll
    for (int a = 0; a < 8; ++a) S[a] = 0.f;

    float* Pr = P + (size_t)rh * SQ * NVD;

    for (int s0 = 0; s0 < SQ; s0 += 32) {
        for (int idx = t; idx < 32 * 64; idx += 256) {
            int tt = idx >> 6, col = idx & 63;
            qs[tt][col] = Q[(size_t)(s0 + tt) * HID + h * 128 + rh * 64 + col];
            ks[tt][col] = K[(size_t)(s0 + tt) * HID + h * 128 + rh * 64 + col];
        }
        for (int idx = t; idx < 32 * 32; idx += 256) {
            int tt = idx >> 5, col = idx & 31;
            vs[tt][col] = V[(size_t)(s0 + tt) * NVD + h * 256 + c0 + col];
        }
        if (t < 32) bs[t] = Beta[(s0 + t) * NHK + h];
        __syncthreads();
        for (int tt = 0; tt < 32; ++tt) {
            float bt = bs[tt];
            float v  = vs[tt][cg];
            float p  = 0.f;
#pragma unroll
            for (int a = 0; a < 8; ++a) {
                float kr = ks[tt][rg + 8 * a];
                float qr = qs[tt][rg + 8 * a];
                S[a] = bt * S[a] + kr * v;
                p += qr * S[a];
            }
#pragma unroll
            for (int off = 4; off; off >>= 1)
                p += __shfl_xor_sync(0xffffffffu, p, off);
            if (rg == 0)
                Pr[(size_t)(s0 + tt) * NVD + h * 256 + c0 + cg] = p;
        }
        __syncthreads();
    }
    if (Sf != nullptr) {
#pragma unroll
        for (int a = 0; a < 8; ++a)
            Sf[(size_t)h * KDIM * VDIM + (size_t)(rh * 64 + rg + 8 * a) * VDIM
               + c0 + cg] = S[a];
    }
}

// combine: O = gate * (P0 + P1), fp16
__global__ __launch_bounds__(256) void combine_kernel(const float* __restrict__ P,
        const float* __restrict__ Gate, __half* __restrict__ O) {
    int i2 = blockIdx.x * 256 + threadIdx.x;    // half2 index
    int idx = i2 * 2;
    int s = idx >> 12;
    int col = idx & 4095;
    int h = col >> 8;
    float g = Gate[s * NHK + h];
    float2 a = *(const float2*)&P[idx];
    float2 b = *(const float2*)&P[SQ * (size_t)NVD + idx];
    __half2 hv;
    hv.x = __float2half_rn(g * (a.x + b.x));
    hv.y = __float2half_rn(g * (a.y + b.y));
    ((__half2*)O)[i2] = hv;
}

// ---------------- launch ------------------------------------------------------
extern "C" void kernel_launch(void* const* d_in, const int* in_sizes, int n_in,
                              void* d_out, int out_size) {
    const float* x   = (const float*)d_in[0];
    const float* Wq  = (const float*)d_in[1];
    const float* Wk  = (const float*)d_in[2];
    const float* Wv  = (const float*)d_in[3];
    const float* Wo  = (const float*)d_in[4];
    const float* Wqc = (const float*)d_in[5];
    const float* bqc = (const float*)d_in[6];
    const float* Wkc = (const float*)d_in[7];
    const float* bkc = (const float*)d_in[8];
    const float* Wg  = (const float*)d_in[9];
    const float* bg  = (const float*)d_in[10];
    const float* Wb  = (const float*)d_in[11];
    const float* bb  = (const float*)d_in[12];
    float* out = (float*)d_out;

    float *dv, *dqc, *dkc, *dgate, *dbeta, *dpart;
    cudaGetSymbolAddress((void**)&dv,    g_v);
    cudaGetSymbolAddress((void**)&dqc,   g_qc);
    cudaGetSymbolAddress((void**)&dkc,   g_kc);
    cudaGetSymbolAddress((void**)&dgate, g_gate);
    cudaGetSymbolAddress((void**)&dbeta, g_beta);
    cudaGetSymbolAddress((void**)&dpart, g_part);

    __half *ah, *woh, *qph, *kph;
    cudaGetSymbolAddress((void**)&ah,  g_ah);
    cudaGetSymbolAddress((void**)&woh, g_woh);
    cudaGetSymbolAddress((void**)&qph, g_qph);
    cudaGetSymbolAddress((void**)&kph, g_kph);

    cudaFuncSetAttribute(proj_fused, cudaFuncAttributeMaxDynamicSharedMemorySize, GSMEM);
    cudaFuncSetAttribute(gemm_mma,   cudaFuncAttributeMaxDynamicSharedMemorySize, GSMEM);
    cudaFuncSetAttribute(conv_mma,   cudaFuncAttributeMaxDynamicSharedMemorySize, GSMEM);

    dim3 blk(256);
    // 0: mega split + gates
    split_all<<<67584, blk>>>(x, (const float2*)Wq, (const float2*)Wk,
                              (const float2*)Wv, (const float2*)Wo, Wqc, Wkc,
                              Wg, bg, Wb, bb, dgate, dbeta);
    // 1: fused q/k/v projections
    proj_fused<<<1024, blk, GSMEM>>>(qph, kph, dv);
    // 2: both convs
    conv_mma<<<dim3(16, 16, 2), blk, GSMEM>>>(bqc, bkc, dqc, dkc);
    // 3: row-split scan (profiled launch)
    float* Sf = (out_size >= OUT_ELEMS + SF_ELEMS) ? (out + OUT_ELEMS) : nullptr;
    scan_kernel<<<256, blk>>>(dqc, dkc, dv, dbeta, dpart, Sf);
    // 4: combine partials + gate -> fp16
    combine_kernel<<<SQ * NVD / 512, blk>>>(dpart, dgate, ah);
    // 5: output projection
    gemm_mma<<<dim3(HID/128, SQ/128), blk, GSMEM>>>(ah, woh, out, SQ, HID, NVD);
}